// round 6
// baseline (speedup 1.0000x reference)
#include <cuda_runtime.h>

#define NN 100000
#define EE 800000
#define DD 128
#define NB_SCAN ((NN + 1023) / 1024)

typedef long long ll;

// ---------------- scratch (device globals; no runtime allocation) ----------------
__device__ int   g_counts[NN];
__device__ int   g_rowptr[NN + 1];
__device__ int   g_cursor[NN];
__device__ int   g_bsums[NB_SCAN];
__device__ float g_dinv[NN];
__device__ int   g_esrc[EE];
__device__ float g_ew[EE];
__device__ int   g_is64;   // 1 if edge_index is int64, 0 if int32
__device__ __align__(16) float g_h0[(size_t)NN * DD];
__device__ __align__(16) float g_h1[(size_t)NN * DD];

// ---------------- edge dtype detection (device-side, capture-safe) ----------------
// int64 indices < 2^31 have zero high words at odd 32-bit positions.
__global__ void k_detect(const unsigned* __restrict__ ei_words, int* __restrict__ flag) {
    __shared__ int zc;
    if (threadIdx.x == 0) zc = 0;
    __syncthreads();
    int z = 0;
    for (int i = threadIdx.x; i < 1024; i += blockDim.x)
        if (ei_words[2 * i + 1] == 0u) z++;
    atomicAdd(&zc, z);
    __syncthreads();
    if (threadIdx.x == 0) *flag = (zc >= 1000) ? 1 : 0;
}

__device__ __forceinline__ int load_idx(const void* ei, int is64, ll pos) {
    if (is64) return (int)((const ll*)ei)[pos];
    return ((const int*)ei)[pos];
}

// ---------------- degree / CSR construction ----------------

__global__ void k_zero(int* __restrict__ counts) {
    int i = blockIdx.x * blockDim.x + threadIdx.x;
    if (i < NN) counts[i] = 0;
}

__global__ void k_count(const void* __restrict__ ei, const int* __restrict__ flag,
                        int* __restrict__ counts) {
    int e = blockIdx.x * blockDim.x + threadIdx.x;
    if (e < EE) {
        int is64 = *flag;
        int dst = load_idx(ei, is64, (ll)EE + e);
        if ((unsigned)dst < (unsigned)NN) atomicAdd(&counts[dst], 1);
    }
}

// Block-wise exclusive scan of counts (1024 items / 256-thread block)
__global__ void k_scan1(const int* __restrict__ counts,
                        int* __restrict__ rowptr,
                        int* __restrict__ bsums) {
    __shared__ int wsums[9];
    int t = threadIdx.x;
    int base = blockIdx.x * 1024 + t * 4;
    int v0 = 0, v1 = 0, v2 = 0, v3 = 0;
    if (base + 0 < NN) v0 = counts[base + 0];
    if (base + 1 < NN) v1 = counts[base + 1];
    if (base + 2 < NN) v2 = counts[base + 2];
    if (base + 3 < NN) v3 = counts[base + 3];
    int loc = v0 + v1 + v2 + v3;

    int lane = t & 31, w = t >> 5;
    int s = loc;
    #pragma unroll
    for (int d = 1; d < 32; d <<= 1) {
        int n = __shfl_up_sync(0xffffffffu, s, d);
        if (lane >= d) s += n;
    }
    if (lane == 31) wsums[w] = s;
    __syncthreads();
    if (t == 0) {
        int acc = 0;
        #pragma unroll
        for (int j = 0; j < 8; j++) { int x = wsums[j]; wsums[j] = acc; acc += x; }
        wsums[8] = acc;
    }
    __syncthreads();
    int excl = s - loc + wsums[w];
    if (base + 0 < NN) { rowptr[base + 0] = excl; excl += v0; }
    if (base + 1 < NN) { rowptr[base + 1] = excl; excl += v1; }
    if (base + 2 < NN) { rowptr[base + 2] = excl; excl += v2; }
    if (base + 3 < NN) { rowptr[base + 3] = excl; excl += v3; }
    if (t == 0) bsums[blockIdx.x] = wsums[8];
}

__global__ void k_scan2(int* __restrict__ bsums, int* __restrict__ rowptr) {
    if (threadIdx.x == 0 && blockIdx.x == 0) {
        int acc = 0;
        for (int b = 0; b < NB_SCAN; b++) { int x = bsums[b]; bsums[b] = acc; acc += x; }
        rowptr[NN] = acc;
    }
}

__global__ void k_scan3(const int* __restrict__ counts,
                        int* __restrict__ rowptr,
                        const int* __restrict__ bsums,
                        int* __restrict__ cursor,
                        float* __restrict__ dinv) {
    int i = blockIdx.x * blockDim.x + threadIdx.x;
    if (i < NN) {
        int r = rowptr[i] + bsums[i >> 10];
        rowptr[i] = r;
        cursor[i] = r;
        dinv[i]   = rsqrtf((float)(counts[i] + 1));   // +1 self-loop
    }
}

__global__ void k_fill(const void* __restrict__ ei, const int* __restrict__ flag,
                       int* __restrict__ cursor,
                       const float* __restrict__ dinv,
                       int* __restrict__ esrc,
                       float* __restrict__ ew) {
    int e = blockIdx.x * blockDim.x + threadIdx.x;
    if (e < EE) {
        int is64 = *flag;
        int s = load_idx(ei, is64, (ll)e);
        int d = load_idx(ei, is64, (ll)EE + e);
        if ((unsigned)s < (unsigned)NN && (unsigned)d < (unsigned)NN) {
            int pos = atomicAdd(&cursor[d], 1);
            if ((unsigned)pos < (unsigned)EE) {
                esrc[pos] = s;
                ew[pos]   = dinv[s] * dinv[d];
            }
        }
    }
}

// ---------------- dense: h0 = X @ W^T ----------------
// 32 nodes per block, 256 threads, 4x4 register tile, K tiled by 32.
__global__ void k_gemm(const float* __restrict__ X,
                       const float* __restrict__ W,
                       float* __restrict__ H0) {
    __shared__ __align__(16) float hs[32][33];
    __shared__ __align__(16) float Ws[32][132];  // row stride 528B (float4-safe)
    int t  = threadIdx.x;
    int nb = blockIdx.x * 32;
    int tx = t & 31;
    int ty = t >> 5;
    float acc[4][4] = {};

    for (int kt = 0; kt < DD; kt += 32) {
        {
            int n  = t >> 3;
            int kq = (t & 7) * 4;
            float4 v = *(const float4*)(X + (size_t)(nb + n) * DD + kt + kq);
            hs[n][kq + 0] = v.x; hs[n][kq + 1] = v.y;
            hs[n][kq + 2] = v.z; hs[n][kq + 3] = v.w;
        }
        #pragma unroll
        for (int r = 0; r < 4; r++) {
            int u  = t + 256 * r;
            int o  = u >> 3;
            int kq = (u & 7) * 4;
            float4 v = *(const float4*)(W + (size_t)o * DD + kt + kq);
            Ws[kq + 0][o] = v.x; Ws[kq + 1][o] = v.y;
            Ws[kq + 2][o] = v.z; Ws[kq + 3][o] = v.w;
        }
        __syncthreads();
        #pragma unroll
        for (int k = 0; k < 32; k++) {
            float4 b4 = *(const float4*)&Ws[k][tx * 4];
            float a0 = hs[ty * 4 + 0][k];
            float a1 = hs[ty * 4 + 1][k];
            float a2 = hs[ty * 4 + 2][k];
            float a3 = hs[ty * 4 + 3][k];
            acc[0][0] += a0 * b4.x; acc[0][1] += a0 * b4.y; acc[0][2] += a0 * b4.z; acc[0][3] += a0 * b4.w;
            acc[1][0] += a1 * b4.x; acc[1][1] += a1 * b4.y; acc[1][2] += a1 * b4.z; acc[1][3] += a1 * b4.w;
            acc[2][0] += a2 * b4.x; acc[2][1] += a2 * b4.y; acc[2][2] += a2 * b4.z; acc[2][3] += a2 * b4.w;
            acc[3][0] += a3 * b4.x; acc[3][1] += a3 * b4.y; acc[3][2] += a3 * b4.z; acc[3][3] += a3 * b4.w;
        }
        __syncthreads();
    }
    #pragma unroll
    for (int j = 0; j < 4; j++) {
        float4 o4 = make_float4(acc[j][0], acc[j][1], acc[j][2], acc[j][3]);
        *(float4*)(H0 + (size_t)(nb + ty * 4 + j) * DD + tx * 4) = o4;
    }
}

// ---------------- sparse hop: one warp per node, lane = float4 of the row ----------------
__global__ void k_hop(const float* __restrict__ hin,
                      float* __restrict__ hout,
                      const int* __restrict__ rowptr,
                      const float* __restrict__ dinv,
                      const int* __restrict__ esrc,
                      const float* __restrict__ ew,
                      const float* __restrict__ bias) {
    int warp = (blockIdx.x * blockDim.x + threadIdx.x) >> 5;
    int lane = threadIdx.x & 31;
    if (warp >= NN) return;
    int i = warp;

    int start = rowptr[i];
    int end   = rowptr[i + 1];
    float di  = dinv[i];
    float sw  = di * di;

    float4 hv = *(const float4*)(hin + (size_t)i * DD + lane * 4);
    float4 acc;
    acc.x = sw * hv.x; acc.y = sw * hv.y; acc.z = sw * hv.z; acc.w = sw * hv.w;

    for (int eb = start; eb < end; eb += 32) {
        int e = eb + lane;
        int s = 0; float w = 0.f;
        if (e < end) { s = esrc[e]; w = ew[e]; }
        int cnt = min(32, end - eb);
        for (int j = 0; j < cnt; j++) {
            int   sj = __shfl_sync(0xffffffffu, s, j);
            float wj = __shfl_sync(0xffffffffu, w, j);
            float4 v = *(const float4*)(hin + (size_t)sj * DD + lane * 4);
            acc.x += wj * v.x; acc.y += wj * v.y; acc.z += wj * v.z; acc.w += wj * v.w;
        }
    }
    if (bias != nullptr) {
        float4 b4 = *(const float4*)(bias + lane * 4);
        acc.x += b4.x; acc.y += b4.y; acc.z += b4.z; acc.w += b4.w;
    }
    *(float4*)(hout + (size_t)i * DD + lane * 4) = acc;
}

// ---------------- launch ----------------
extern "C" void kernel_launch(void* const* d_in, const int* in_sizes, int n_in,
                              void* d_out, int out_size) {
    // Bind inputs by element-count signature (robust to metadata ordering).
    const float* x  = (const float*)d_in[0];
    const void*  ei = (const void*)d_in[1];
    const float* W  = (const float*)d_in[2];
    const float* b  = (const float*)d_in[3];
    for (int i = 0; i < n_in; i++) {
        switch (in_sizes[i]) {
            case NN * DD:   x  = (const float*)d_in[i]; break;   // 12,800,000
            case 2 * EE:    ei = (const void*)d_in[i];  break;   //  1,600,000
            case DD * DD:   W  = (const float*)d_in[i]; break;   //     16,384
            case DD:        b  = (const float*)d_in[i]; break;   //        128
            default: break;
        }
    }
    float* out = (float*)d_out;
    (void)out_size;

    void *p_counts, *p_rowptr, *p_cursor, *p_bsums, *p_dinv, *p_esrc, *p_ew, *p_h0, *p_h1, *p_is64;
    cudaGetSymbolAddress(&p_counts, g_counts);
    cudaGetSymbolAddress(&p_rowptr, g_rowptr);
    cudaGetSymbolAddress(&p_cursor, g_cursor);
    cudaGetSymbolAddress(&p_bsums,  g_bsums);
    cudaGetSymbolAddress(&p_dinv,   g_dinv);
    cudaGetSymbolAddress(&p_esrc,   g_esrc);
    cudaGetSymbolAddress(&p_ew,     g_ew);
    cudaGetSymbolAddress(&p_h0,     g_h0);
    cudaGetSymbolAddress(&p_h1,     g_h1);
    cudaGetSymbolAddress(&p_is64,   g_is64);
    int*   counts = (int*)p_counts;
    int*   rowptr = (int*)p_rowptr;
    int*   cursor = (int*)p_cursor;
    int*   bsums  = (int*)p_bsums;
    float* dinv   = (float*)p_dinv;
    int*   esrc   = (int*)p_esrc;
    float* ew     = (float*)p_ew;
    float* h0     = (float*)p_h0;
    float* h1     = (float*)p_h1;
    int*   is64   = (int*)p_is64;

    k_detect<<<1, 256>>>((const unsigned*)ei, is64);
    k_zero  <<<(NN + 255) / 256, 256>>>(counts);
    k_count <<<(EE + 255) / 256, 256>>>(ei, is64, counts);
    k_scan1 <<<NB_SCAN, 256>>>(counts, rowptr, bsums);
    k_scan2 <<<1, 32>>>(bsums, rowptr);
    k_scan3 <<<(NN + 255) / 256, 256>>>(counts, rowptr, bsums, cursor, dinv);
    k_fill  <<<(EE + 255) / 256, 256>>>(ei, is64, cursor, dinv, esrc, ew);

    k_gemm<<<NN / 32, 256>>>(x, W, h0);      // h0 = X W^T

    const int hop_blocks = (NN * 32 + 255) / 256;
    k_hop<<<hop_blocks, 256>>>(h0, h1, rowptr, dinv, esrc, ew, nullptr);  // hop 1
    k_hop<<<hop_blocks, 256>>>(h1, h0, rowptr, dinv, esrc, ew, nullptr);  // hop 2
    k_hop<<<hop_blocks, 256>>>(h0, out, rowptr, dinv, esrc, ew, b);       // hop 3 (+bias)
}

// round 8
// speedup vs baseline: 1.0377x; 1.0377x over previous
#include <cuda_runtime.h>

#define NN 100000
#define EE 800000
#define DD 128
#define NB_SCAN ((NN + 1023) / 1024)

typedef long long ll;
typedef unsigned long long ull;

// ---------------- scratch (device globals; no runtime allocation) ----------------
__device__ int   g_counts[NN];
__device__ int   g_rowptr[NN + 1];
__device__ int   g_cursor[NN];
__device__ int   g_bsums[NB_SCAN];
__device__ float g_dinv[NN];
__device__ int   g_esrc[EE];
__device__ float g_ew[EE];
__device__ int   g_is64;
__device__ __align__(16) float g_Wt[DD * DD];          // W transposed: Wt[k][col]
__device__ __align__(16) float g_h0[(size_t)NN * DD];
__device__ __align__(16) float g_h1[(size_t)NN * DD];

// ---------------- f32x2 helpers ----------------
__device__ __forceinline__ ull ffma2(ull a, ull b, ull c) {
    ull d;
    asm("fma.rn.f32x2 %0, %1, %2, %3;" : "=l"(d) : "l"(a), "l"(b), "l"(c));
    return d;
}
__device__ __forceinline__ ull dupf(float x) {
    ull d; asm("mov.b64 %0, {%1, %1};" : "=l"(d) : "f"(x)); return d;
}
__device__ __forceinline__ float2 ull2f2(ull v) {
    float2 r; asm("mov.b64 {%0, %1}, %2;" : "=f"(r.x), "=f"(r.y) : "l"(v)); return r;
}

// ---------------- dtype detect + zero counts (fused) ----------------
// int64 indices < 2^31 have zero high words at odd 32-bit positions.
__global__ void k_detect_zero(const unsigned* __restrict__ ei_words,
                              int* __restrict__ flag,
                              int* __restrict__ counts) {
    int i = blockIdx.x * blockDim.x + threadIdx.x;
    if (i < NN) counts[i] = 0;
    if (blockIdx.x == 0) {
        __shared__ int zc;
        if (threadIdx.x == 0) zc = 0;
        __syncthreads();
        int z = 0;
        for (int j = threadIdx.x; j < 1024; j += blockDim.x)
            if (ei_words[2 * j + 1] == 0u) z++;
        atomicAdd(&zc, z);
        __syncthreads();
        if (threadIdx.x == 0) *flag = (zc >= 1000) ? 1 : 0;
    }
}

__device__ __forceinline__ int load_idx(const void* ei, int is64, ll pos) {
    if (is64) return (int)((const ll*)ei)[pos];
    return ((const int*)ei)[pos];
}

// ---------------- degree / CSR construction ----------------

__global__ void k_count(const void* __restrict__ ei, const int* __restrict__ flag,
                        int* __restrict__ counts) {
    int e = blockIdx.x * blockDim.x + threadIdx.x;
    if (e < EE) {
        int is64 = *flag;
        int dst = load_idx(ei, is64, (ll)EE + e);
        if ((unsigned)dst < (unsigned)NN) atomicAdd(&counts[dst], 1);
    }
}

__global__ void k_scan1(const int* __restrict__ counts,
                        int* __restrict__ rowptr,
                        int* __restrict__ bsums) {
    __shared__ int wsums[9];
    int t = threadIdx.x;
    int base = blockIdx.x * 1024 + t * 4;
    int v0 = 0, v1 = 0, v2 = 0, v3 = 0;
    if (base + 0 < NN) v0 = counts[base + 0];
    if (base + 1 < NN) v1 = counts[base + 1];
    if (base + 2 < NN) v2 = counts[base + 2];
    if (base + 3 < NN) v3 = counts[base + 3];
    int loc = v0 + v1 + v2 + v3;

    int lane = t & 31, w = t >> 5;
    int s = loc;
    #pragma unroll
    for (int d = 1; d < 32; d <<= 1) {
        int n = __shfl_up_sync(0xffffffffu, s, d);
        if (lane >= d) s += n;
    }
    if (lane == 31) wsums[w] = s;
    __syncthreads();
    if (t == 0) {
        int acc = 0;
        #pragma unroll
        for (int j = 0; j < 8; j++) { int x = wsums[j]; wsums[j] = acc; acc += x; }
        wsums[8] = acc;
    }
    __syncthreads();
    int excl = s - loc + wsums[w];
    if (base + 0 < NN) { rowptr[base + 0] = excl; excl += v0; }
    if (base + 1 < NN) { rowptr[base + 1] = excl; excl += v1; }
    if (base + 2 < NN) { rowptr[base + 2] = excl; excl += v2; }
    if (base + 3 < NN) { rowptr[base + 3] = excl; excl += v3; }
    if (t == 0) bsums[blockIdx.x] = wsums[8];
}

__global__ void k_scan2(int* __restrict__ bsums, int* __restrict__ rowptr) {
    if (threadIdx.x == 0 && blockIdx.x == 0) {
        int acc = 0;
        for (int b = 0; b < NB_SCAN; b++) { int x = bsums[b]; bsums[b] = acc; acc += x; }
        rowptr[NN] = acc;
    }
}

__global__ void k_scan3(const int* __restrict__ counts,
                        int* __restrict__ rowptr,
                        const int* __restrict__ bsums,
                        int* __restrict__ cursor,
                        float* __restrict__ dinv) {
    int i = blockIdx.x * blockDim.x + threadIdx.x;
    if (i < NN) {
        int r = rowptr[i] + bsums[i >> 10];
        rowptr[i] = r;
        cursor[i] = r;
        dinv[i]   = rsqrtf((float)(counts[i] + 1));   // +1 self-loop
    }
}

__global__ void k_fill(const void* __restrict__ ei, const int* __restrict__ flag,
                       int* __restrict__ cursor,
                       const float* __restrict__ dinv,
                       int* __restrict__ esrc,
                       float* __restrict__ ew) {
    int e = blockIdx.x * blockDim.x + threadIdx.x;
    if (e < EE) {
        int is64 = *flag;
        int s = load_idx(ei, is64, (ll)e);
        int d = load_idx(ei, is64, (ll)EE + e);
        if ((unsigned)s < (unsigned)NN && (unsigned)d < (unsigned)NN) {
            int pos = atomicAdd(&cursor[d], 1);
            if ((unsigned)pos < (unsigned)EE) {
                esrc[pos] = s;
                ew[pos]   = dinv[s] * dinv[d];
            }
        }
    }
}

// ---------------- W transpose: Wt[k][col] = W[col][k] ----------------
__global__ void k_wt(const float* __restrict__ W, float* __restrict__ Wt) {
    int i = blockIdx.x * blockDim.x + threadIdx.x;   // 16384 elems
    if (i < DD * DD) {
        int k = i & (DD - 1);
        int c = i >> 7;
        Wt[k * DD + c] = W[c * DD + k];
    }
}

// ---------------- dense: H0 = X @ W^T  (FFMA2 / f32x2) ----------------
// 64 rows x 128 cols per block, 256 threads, per-thread 8 rows x 4 cols.
// A stored pre-duplicated {a,a}; B consumed as natural col-pairs.
__global__ void k_gemm(const float* __restrict__ X,
                       const float* __restrict__ Wt,
                       float* __restrict__ H0) {
    __shared__ __align__(16) ull   hsT2[32][66];   // [k][row] dup pairs, 528B rows
    __shared__ __align__(16) float Ws[32][132];    // [k][col], 528B rows
    int t  = threadIdx.x;
    int nb = blockIdx.x * 64;
    int tx = t & 31;    // col quad: cols tx*4 .. tx*4+3
    int ty = t >> 5;    // row octet: rows ty*8 .. ty*8+7
    ull acc[8][2] = {};

    for (int kt = 0; kt < DD; kt += 32) {
        // X tile: 64 rows x 32 k, transposed + duplicated
        #pragma unroll
        for (int r = 0; r < 2; r++) {
            int u   = t + 256 * r;
            int row = u >> 3;
            int kq  = (u & 7) * 4;
            int gr  = nb + row; if (gr >= NN) gr = NN - 1;
            float4 v = *(const float4*)(X + (size_t)gr * DD + kt + kq);
            hsT2[kq + 0][row] = dupf(v.x);
            hsT2[kq + 1][row] = dupf(v.y);
            hsT2[kq + 2][row] = dupf(v.z);
            hsT2[kq + 3][row] = dupf(v.w);
        }
        // Wt tile: 32 k x 128 cols (coalesced, conflict-free)
        #pragma unroll
        for (int r = 0; r < 4; r++) {
            int u  = t + 256 * r;
            int k  = u >> 5;
            int cq = (u & 31) * 4;
            float4 v = *(const float4*)(Wt + (size_t)(kt + k) * DD + cq);
            *(float4*)&Ws[k][cq] = v;
        }
        __syncthreads();
        #pragma unroll 8
        for (int k = 0; k < 32; k++) {
            ulonglong2 b01 = *(const ulonglong2*)&Ws[k][tx * 4];   // {c0c1, c2c3}
            const ulonglong2* ap = (const ulonglong2*)&hsT2[k][ty * 8];
            #pragma unroll
            for (int q = 0; q < 4; q++) {
                ulonglong2 a2 = ap[q];   // rows 2q, 2q+1 (duplicated)
                acc[2*q  ][0] = ffma2(a2.x, b01.x, acc[2*q  ][0]);
                acc[2*q  ][1] = ffma2(a2.x, b01.y, acc[2*q  ][1]);
                acc[2*q+1][0] = ffma2(a2.y, b01.x, acc[2*q+1][0]);
                acc[2*q+1][1] = ffma2(a2.y, b01.y, acc[2*q+1][1]);
            }
        }
        __syncthreads();
    }
    #pragma unroll
    for (int j = 0; j < 8; j++) {
        int gr = nb + ty * 8 + j;
        if (gr < NN) {
            float2 p0 = ull2f2(acc[j][0]);
            float2 p1 = ull2f2(acc[j][1]);
            float4 o = make_float4(p0.x, p0.y, p1.x, p1.y);
            *(float4*)(H0 + (size_t)gr * DD + tx * 4) = o;
        }
    }
}

// ---------------- sparse hop: one warp per node, lane = float4 of the row ----------------
__global__ void k_hop(const float* __restrict__ hin,
                      float* __restrict__ hout,
                      const int* __restrict__ rowptr,
                      const float* __restrict__ dinv,
                      const int* __restrict__ esrc,
                      const float* __restrict__ ew,
                      const float* __restrict__ bias) {
    int warp = (blockIdx.x * blockDim.x + threadIdx.x) >> 5;
    int lane = threadIdx.x & 31;
    if (warp >= NN) return;
    int i = warp;

    int start = rowptr[i];
    int end   = rowptr[i + 1];
    float di  = dinv[i];
    float sw  = di * di;

    float4 hv = *(const float4*)(hin + (size_t)i * DD + lane * 4);
    float4 acc;
    acc.x = sw * hv.x; acc.y = sw * hv.y; acc.z = sw * hv.z; acc.w = sw * hv.w;

    for (int eb = start; eb < end; eb += 32) {
        int e = eb + lane;
        int s = 0; float w = 0.f;
        if (e < end) { s = esrc[e]; w = ew[e]; }
        int cnt = min(32, end - eb);
        int j = 0;
        for (; j + 2 <= cnt; j += 2) {
            int   s0 = __shfl_sync(0xffffffffu, s, j);
            int   s1 = __shfl_sync(0xffffffffu, s, j + 1);
            float w0 = __shfl_sync(0xffffffffu, w, j);
            float w1 = __shfl_sync(0xffffffffu, w, j + 1);
            float4 v0 = *(const float4*)(hin + (size_t)s0 * DD + lane * 4);
            float4 v1 = *(const float4*)(hin + (size_t)s1 * DD + lane * 4);
            acc.x += w0 * v0.x + w1 * v1.x;
            acc.y += w0 * v0.y + w1 * v1.y;
            acc.z += w0 * v0.z + w1 * v1.z;
            acc.w += w0 * v0.w + w1 * v1.w;
        }
        if (j < cnt) {
            int   sj = __shfl_sync(0xffffffffu, s, j);
            float wj = __shfl_sync(0xffffffffu, w, j);
            float4 v = *(const float4*)(hin + (size_t)sj * DD + lane * 4);
            acc.x += wj * v.x; acc.y += wj * v.y; acc.z += wj * v.z; acc.w += wj * v.w;
        }
    }
    if (bias != nullptr) {
        float4 b4 = *(const float4*)(bias + lane * 4);
        acc.x += b4.x; acc.y += b4.y; acc.z += b4.z; acc.w += b4.w;
    }
    *(float4*)(hout + (size_t)i * DD + lane * 4) = acc;
}

// ---------------- launch ----------------
extern "C" void kernel_launch(void* const* d_in, const int* in_sizes, int n_in,
                              void* d_out, int out_size) {
    const float* x  = (const float*)d_in[0];
    const void*  ei = (const void*)d_in[1];
    const float* W  = (const float*)d_in[2];
    const float* b  = (const float*)d_in[3];
    for (int i = 0; i < n_in; i++) {
        switch (in_sizes[i]) {
            case NN * DD:   x  = (const float*)d_in[i]; break;
            case 2 * EE:    ei = (const void*)d_in[i];  break;
            case DD * DD:   W  = (const float*)d_in[i]; break;
            case DD:        b  = (const float*)d_in[i]; break;
            default: break;
        }
    }
    float* out = (float*)d_out;
    (void)out_size;

    void *p_counts, *p_rowptr, *p_cursor, *p_bsums, *p_dinv, *p_esrc, *p_ew,
         *p_h0, *p_h1, *p_is64, *p_wt;
    cudaGetSymbolAddress(&p_counts, g_counts);
    cudaGetSymbolAddress(&p_rowptr, g_rowptr);
    cudaGetSymbolAddress(&p_cursor, g_cursor);
    cudaGetSymbolAddress(&p_bsums,  g_bsums);
    cudaGetSymbolAddress(&p_dinv,   g_dinv);
    cudaGetSymbolAddress(&p_esrc,   g_esrc);
    cudaGetSymbolAddress(&p_ew,     g_ew);
    cudaGetSymbolAddress(&p_h0,     g_h0);
    cudaGetSymbolAddress(&p_h1,     g_h1);
    cudaGetSymbolAddress(&p_is64,   g_is64);
    cudaGetSymbolAddress(&p_wt,     g_Wt);
    int*   counts = (int*)p_counts;
    int*   rowptr = (int*)p_rowptr;
    int*   cursor = (int*)p_cursor;
    int*   bsums  = (int*)p_bsums;
    float* dinv   = (float*)p_dinv;
    int*   esrc   = (int*)p_esrc;
    float* ew     = (float*)p_ew;
    float* h0     = (float*)p_h0;
    float* h1     = (float*)p_h1;
    int*   is64   = (int*)p_is64;
    float* wt     = (float*)p_wt;

    k_detect_zero<<<(NN + 255) / 256, 256>>>((const unsigned*)ei, is64, counts);
    k_wt   <<<(DD * DD + 255) / 256, 256>>>(W, wt);
    k_count<<<(EE + 255) / 256, 256>>>(ei, is64, counts);
    k_scan1<<<NB_SCAN, 256>>>(counts, rowptr, bsums);
    k_scan2<<<1, 32>>>(bsums, rowptr);
    k_scan3<<<(NN + 255) / 256, 256>>>(counts, rowptr, bsums, cursor, dinv);
    k_fill <<<(EE + 255) / 256, 256>>>(ei, is64, cursor, dinv, esrc, ew);

    k_gemm<<<(NN + 63) / 64, 256>>>(x, wt, h0);   // h0 = X W^T

    const int hop_blocks = (NN * 32 + 255) / 256;
    k_hop<<<hop_blocks, 256>>>(h0, h1, rowptr, dinv, esrc, ew, nullptr);  // hop 1
    k_hop<<<hop_blocks, 256>>>(h1, h0, rowptr, dinv, esrc, ew, nullptr);  // hop 2
    k_hop<<<hop_blocks, 256>>>(h0, out, rowptr, dinv, esrc, ew, b);       // hop 3 (+bias)
}

// round 10
// speedup vs baseline: 1.0379x; 1.0001x over previous
#include <cuda_runtime.h>

#define NN 100000
#define EE 800000
#define DD 128
#define NB_SCAN ((NN + 1023) / 1024)

typedef long long ll;
typedef unsigned long long ull;

// ---------------- scratch (device globals; no runtime allocation) ----------------
__device__ int   g_counts[NN];
__device__ int   g_rowptr[NN + 1];
__device__ int   g_cursor[NN];
__device__ int   g_bsums[NB_SCAN];
__device__ float g_dinv[NN];
__device__ int   g_esrc[EE];
__device__ float g_ew[EE];
__device__ int   g_is64;
__device__ __align__(16) float g_Wt[DD * DD];
__device__ __align__(16) float g_h0[(size_t)NN * DD];
__device__ __align__(16) float g_h1[(size_t)NN * DD];

// ---------------- f32x2 helpers ----------------
__device__ __forceinline__ ull ffma2(ull a, ull b, ull c) {
    ull d;
    asm("fma.rn.f32x2 %0, %1, %2, %3;" : "=l"(d) : "l"(a), "l"(b), "l"(c));
    return d;
}
__device__ __forceinline__ ull dupf(float x) {
    ull d; asm("mov.b64 %0, {%1, %1};" : "=l"(d) : "f"(x)); return d;
}
__device__ __forceinline__ float2 ull2f2(ull v) {
    float2 r; asm("mov.b64 {%0, %1}, %2;" : "=f"(r.x), "=f"(r.y) : "l"(v)); return r;
}

// ---------------- dtype detect + zero counts (fused) ----------------
__global__ void k_detect_zero(const unsigned* __restrict__ ei_words,
                              int* __restrict__ flag,
                              int* __restrict__ counts) {
    int i = blockIdx.x * blockDim.x + threadIdx.x;
    if (i < NN) counts[i] = 0;
    if (blockIdx.x == 0) {
        __shared__ int zc;
        if (threadIdx.x == 0) zc = 0;
        __syncthreads();
        int z = 0;
        for (int j = threadIdx.x; j < 1024; j += blockDim.x)
            if (ei_words[2 * j + 1] == 0u) z++;
        atomicAdd(&zc, z);
        __syncthreads();
        if (threadIdx.x == 0) *flag = (zc >= 1000) ? 1 : 0;
    }
}

__device__ __forceinline__ int load_idx(const void* ei, int is64, ll pos) {
    if (is64) return (int)((const ll*)ei)[pos];
    return ((const int*)ei)[pos];
}

// ---------------- degree / CSR construction ----------------

__global__ void k_count(const void* __restrict__ ei, const int* __restrict__ flag,
                        int* __restrict__ counts) {
    int e = blockIdx.x * blockDim.x + threadIdx.x;
    if (e < EE) {
        int is64 = *flag;
        int dst = load_idx(ei, is64, (ll)EE + e);
        if ((unsigned)dst < (unsigned)NN) atomicAdd(&counts[dst], 1);
    }
}

__global__ void k_scan1(const int* __restrict__ counts,
                        int* __restrict__ rowptr,
                        int* __restrict__ bsums) {
    __shared__ int wsums[9];
    int t = threadIdx.x;
    int base = blockIdx.x * 1024 + t * 4;
    int v0 = 0, v1 = 0, v2 = 0, v3 = 0;
    if (base + 0 < NN) v0 = counts[base + 0];
    if (base + 1 < NN) v1 = counts[base + 1];
    if (base + 2 < NN) v2 = counts[base + 2];
    if (base + 3 < NN) v3 = counts[base + 3];
    int loc = v0 + v1 + v2 + v3;

    int lane = t & 31, w = t >> 5;
    int s = loc;
    #pragma unroll
    for (int d = 1; d < 32; d <<= 1) {
        int n = __shfl_up_sync(0xffffffffu, s, d);
        if (lane >= d) s += n;
    }
    if (lane == 31) wsums[w] = s;
    __syncthreads();
    if (t == 0) {
        int acc = 0;
        #pragma unroll
        for (int j = 0; j < 8; j++) { int x = wsums[j]; wsums[j] = acc; acc += x; }
        wsums[8] = acc;
    }
    __syncthreads();
    int excl = s - loc + wsums[w];
    if (base + 0 < NN) { rowptr[base + 0] = excl; excl += v0; }
    if (base + 1 < NN) { rowptr[base + 1] = excl; excl += v1; }
    if (base + 2 < NN) { rowptr[base + 2] = excl; excl += v2; }
    if (base + 3 < NN) { rowptr[base + 3] = excl; excl += v3; }
    if (t == 0) bsums[blockIdx.x] = wsums[8];
}

// warp-parallel scan over NB_SCAN block sums
__global__ void k_scan2(int* __restrict__ bsums, int* __restrict__ rowptr) {
    int lane = threadIdx.x & 31;
    int carry = 0;
    for (int base = 0; base < NB_SCAN; base += 32) {
        int v = (base + lane < NB_SCAN) ? bsums[base + lane] : 0;
        int sIncl = v;
        #pragma unroll
        for (int d = 1; d < 32; d <<= 1) {
            int n = __shfl_up_sync(0xffffffffu, sIncl, d);
            if (lane >= d) sIncl += n;
        }
        if (base + lane < NB_SCAN) bsums[base + lane] = carry + sIncl - v;
        carry += __shfl_sync(0xffffffffu, sIncl, 31);
    }
    if (lane == 0) rowptr[NN] = carry;
}

__global__ void k_scan3(const int* __restrict__ counts,
                        int* __restrict__ rowptr,
                        const int* __restrict__ bsums,
                        int* __restrict__ cursor,
                        float* __restrict__ dinv) {
    int i = blockIdx.x * blockDim.x + threadIdx.x;
    if (i < NN) {
        int r = rowptr[i] + bsums[i >> 10];
        rowptr[i] = r;
        cursor[i] = r;
        dinv[i]   = rsqrtf((float)(counts[i] + 1));   // +1 self-loop
    }
}

__global__ void k_fill(const void* __restrict__ ei, const int* __restrict__ flag,
                       int* __restrict__ cursor,
                       const float* __restrict__ dinv,
                       int* __restrict__ esrc,
                       float* __restrict__ ew) {
    int e = blockIdx.x * blockDim.x + threadIdx.x;
    if (e < EE) {
        int is64 = *flag;
        int s = load_idx(ei, is64, (ll)e);
        int d = load_idx(ei, is64, (ll)EE + e);
        if ((unsigned)s < (unsigned)NN && (unsigned)d < (unsigned)NN) {
            int pos = atomicAdd(&cursor[d], 1);
            if ((unsigned)pos < (unsigned)EE) {
                esrc[pos] = s;
                ew[pos]   = dinv[s] * dinv[d];
            }
        }
    }
}

// ---------------- W transpose ----------------
__global__ void k_wt(const float* __restrict__ W, float* __restrict__ Wt) {
    int i = blockIdx.x * blockDim.x + threadIdx.x;
    if (i < DD * DD) {
        int k = i & (DD - 1);
        int c = i >> 7;
        Wt[k * DD + c] = W[c * DD + k];
    }
}

// ---------------- dense: H0 = X @ W^T  (FFMA2 / f32x2) ----------------
__global__ void k_gemm(const float* __restrict__ X,
                       const float* __restrict__ Wt,
                       float* __restrict__ H0) {
    __shared__ __align__(16) ull   hsT2[32][66];
    __shared__ __align__(16) float Ws[32][132];
    int t  = threadIdx.x;
    int nb = blockIdx.x * 64;
    int tx = t & 31;
    int ty = t >> 5;
    ull acc[8][2] = {};

    for (int kt = 0; kt < DD; kt += 32) {
        #pragma unroll
        for (int r = 0; r < 2; r++) {
            int u   = t + 256 * r;
            int row = u >> 3;
            int kq  = (u & 7) * 4;
            int gr  = nb + row; if (gr >= NN) gr = NN - 1;
            float4 v = *(const float4*)(X + (size_t)gr * DD + kt + kq);
            hsT2[kq + 0][row] = dupf(v.x);
            hsT2[kq + 1][row] = dupf(v.y);
            hsT2[kq + 2][row] = dupf(v.z);
            hsT2[kq + 3][row] = dupf(v.w);
        }
        #pragma unroll
        for (int r = 0; r < 4; r++) {
            int u  = t + 256 * r;
            int k  = u >> 5;
            int cq = (u & 31) * 4;
            float4 v = *(const float4*)(Wt + (size_t)(kt + k) * DD + cq);
            *(float4*)&Ws[k][cq] = v;
        }
        __syncthreads();
        #pragma unroll 8
        for (int k = 0; k < 32; k++) {
            ulonglong2 b01 = *(const ulonglong2*)&Ws[k][tx * 4];
            const ulonglong2* ap = (const ulonglong2*)&hsT2[k][ty * 8];
            #pragma unroll
            for (int q = 0; q < 4; q++) {
                ulonglong2 a2 = ap[q];
                acc[2*q  ][0] = ffma2(a2.x, b01.x, acc[2*q  ][0]);
                acc[2*q  ][1] = ffma2(a2.x, b01.y, acc[2*q  ][1]);
                acc[2*q+1][0] = ffma2(a2.y, b01.x, acc[2*q+1][0]);
                acc[2*q+1][1] = ffma2(a2.y, b01.y, acc[2*q+1][1]);
            }
        }
        __syncthreads();
    }
    #pragma unroll
    for (int j = 0; j < 8; j++) {
        int gr = nb + ty * 8 + j;
        if (gr < NN) {
            float2 p0 = ull2f2(acc[j][0]);
            float2 p1 = ull2f2(acc[j][1]);
            float4 o = make_float4(p0.x, p0.y, p1.x, p1.y);
            *(float4*)(H0 + (size_t)gr * DD + tx * 4) = o;
        }
    }
}

// ---------------- sparse hop: one warp per node, unroll-4 gather for MLP ----------------
__global__ void k_hop(const float* __restrict__ hin,
                      float* __restrict__ hout,
                      const int* __restrict__ rowptr,
                      const float* __restrict__ dinv,
                      const int* __restrict__ esrc,
                      const float* __restrict__ ew,
                      const float* __restrict__ bias) {
    int warp = (blockIdx.x * blockDim.x + threadIdx.x) >> 5;
    int lane = threadIdx.x & 31;
    if (warp >= NN) return;
    int i = warp;

    int start = rowptr[i];
    int end   = rowptr[i + 1];
    float di  = dinv[i];
    float sw  = di * di;

    float4 hv = *(const float4*)(hin + (size_t)i * DD + lane * 4);
    float4 acc;
    acc.x = sw * hv.x; acc.y = sw * hv.y; acc.z = sw * hv.z; acc.w = sw * hv.w;

    for (int eb = start; eb < end; eb += 32) {
        int e = eb + lane;
        int s = 0; float w = 0.f;
        if (e < end) { s = esrc[e]; w = ew[e]; }
        int cnt = min(32, end - eb);
        int j = 0;
        for (; j + 4 <= cnt; j += 4) {
            int   s0 = __shfl_sync(0xffffffffu, s, j);
            int   s1 = __shfl_sync(0xffffffffu, s, j + 1);
            int   s2 = __shfl_sync(0xffffffffu, s, j + 2);
            int   s3 = __shfl_sync(0xffffffffu, s, j + 3);
            float w0 = __shfl_sync(0xffffffffu, w, j);
            float w1 = __shfl_sync(0xffffffffu, w, j + 1);
            float w2 = __shfl_sync(0xffffffffu, w, j + 2);
            float w3 = __shfl_sync(0xffffffffu, w, j + 3);
            float4 v0 = *(const float4*)(hin + (size_t)s0 * DD + lane * 4);
            float4 v1 = *(const float4*)(hin + (size_t)s1 * DD + lane * 4);
            float4 v2 = *(const float4*)(hin + (size_t)s2 * DD + lane * 4);
            float4 v3 = *(const float4*)(hin + (size_t)s3 * DD + lane * 4);
            acc.x += w0 * v0.x; acc.y += w0 * v0.y; acc.z += w0 * v0.z; acc.w += w0 * v0.w;
            acc.x += w1 * v1.x; acc.y += w1 * v1.y; acc.z += w1 * v1.z; acc.w += w1 * v1.w;
            acc.x += w2 * v2.x; acc.y += w2 * v2.y; acc.z += w2 * v2.z; acc.w += w2 * v2.w;
            acc.x += w3 * v3.x; acc.y += w3 * v3.y; acc.z += w3 * v3.z; acc.w += w3 * v3.w;
        }
        if (j + 2 <= cnt) {
            int   s0 = __shfl_sync(0xffffffffu, s, j);
            int   s1 = __shfl_sync(0xffffffffu, s, j + 1);
            float w0 = __shfl_sync(0xffffffffu, w, j);
            float w1 = __shfl_sync(0xffffffffu, w, j + 1);
            float4 v0 = *(const float4*)(hin + (size_t)s0 * DD + lane * 4);
            float4 v1 = *(const float4*)(hin + (size_t)s1 * DD + lane * 4);
            acc.x += w0 * v0.x + w1 * v1.x;
            acc.y += w0 * v0.y + w1 * v1.y;
            acc.z += w0 * v0.z + w1 * v1.z;
            acc.w += w0 * v0.w + w1 * v1.w;
            j += 2;
        }
        if (j < cnt) {
            int   sj = __shfl_sync(0xffffffffu, s, j);
            float wj = __shfl_sync(0xffffffffu, w, j);
            float4 v = *(const float4*)(hin + (size_t)sj * DD + lane * 4);
            acc.x += wj * v.x; acc.y += wj * v.y; acc.z += wj * v.z; acc.w += wj * v.w;
        }
    }
    if (bias != nullptr) {
        float4 b4 = *(const float4*)(bias + lane * 4);
        acc.x += b4.x; acc.y += b4.y; acc.z += b4.z; acc.w += b4.w;
    }
    *(float4*)(hout + (size_t)i * DD + lane * 4) = acc;
}

// ---------------- launch ----------------
extern "C" void kernel_launch(void* const* d_in, const int* in_sizes, int n_in,
                              void* d_out, int out_size) {
    const float* x  = (const float*)d_in[0];
    const void*  ei = (const void*)d_in[1];
    const float* W  = (const float*)d_in[2];
    const float* b  = (const float*)d_in[3];
    for (int i = 0; i < n_in; i++) {
        switch (in_sizes[i]) {
            case NN * DD:   x  = (const float*)d_in[i]; break;
            case 2 * EE:    ei = (const void*)d_in[i];  break;
            case DD * DD:   W  = (const float*)d_in[i]; break;
            case DD:        b  = (const float*)d_in[i]; break;
            default: break;
        }
    }
    float* out = (float*)d_out;
    (void)out_size;

    void *p_counts, *p_rowptr, *p_cursor, *p_bsums, *p_dinv, *p_esrc, *p_ew,
         *p_h0, *p_h1, *p_is64, *p_wt;
    cudaGetSymbolAddress(&p_counts, g_counts);
    cudaGetSymbolAddress(&p_rowptr, g_rowptr);
    cudaGetSymbolAddress(&p_cursor, g_cursor);
    cudaGetSymbolAddress(&p_bsums,  g_bsums);
    cudaGetSymbolAddress(&p_dinv,   g_dinv);
    cudaGetSymbolAddress(&p_esrc,   g_esrc);
    cudaGetSymbolAddress(&p_ew,     g_ew);
    cudaGetSymbolAddress(&p_h0,     g_h0);
    cudaGetSymbolAddress(&p_h1,     g_h1);
    cudaGetSymbolAddress(&p_is64,   g_is64);
    cudaGetSymbolAddress(&p_wt,     g_Wt);
    int*   counts = (int*)p_counts;
    int*   rowptr = (int*)p_rowptr;
    int*   cursor = (int*)p_cursor;
    int*   bsums  = (int*)p_bsums;
    float* dinv   = (float*)p_dinv;
    int*   esrc   = (int*)p_esrc;
    float* ew     = (float*)p_ew;
    float* h0     = (float*)p_h0;
    float* h1     = (float*)p_h1;
    int*   is64   = (int*)p_is64;
    float* wt     = (float*)p_wt;

    k_detect_zero<<<(NN + 255) / 256, 256>>>((const unsigned*)ei, is64, counts);
    k_wt   <<<(DD * DD + 255) / 256, 256>>>(W, wt);
    k_count<<<(EE + 255) / 256, 256>>>(ei, is64, counts);
    k_scan1<<<NB_SCAN, 256>>>(counts, rowptr, bsums);
    k_scan2<<<1, 32>>>(bsums, rowptr);
    k_scan3<<<(NN + 255) / 256, 256>>>(counts, rowptr, bsums, cursor, dinv);
    k_fill <<<(EE + 255) / 256, 256>>>(ei, is64, cursor, dinv, esrc, ew);

    k_gemm<<<(NN + 63) / 64, 256>>>(x, wt, h0);   // h0 = X W^T

    const int hop_blocks = (NN * 32 + 255) / 256;
    k_hop<<<hop_blocks, 256>>>(h0, h1, rowptr, dinv, esrc, ew, nullptr);  // hop 1
    k_hop<<<hop_blocks, 256>>>(h1, h0, rowptr, dinv, esrc, ew, nullptr);  // hop 2
    k_hop<<<hop_blocks, 256>>>(h0, out, rowptr, dinv, esrc, ew, b);       // hop 3 (+bias)
}

// round 11
// speedup vs baseline: 1.1029x; 1.0626x over previous
#include <cuda_runtime.h>

#define NN 100000
#define EE 800000
#define DD 128
#define NB_SCAN ((NN + 1023) / 1024)

typedef long long ll;
typedef unsigned long long ull;

// ---------------- scratch (device globals; no runtime allocation) ----------------
__device__ int   g_counts[NN];
__device__ int   g_rowptr[NN + 1];
__device__ int   g_cursor[NN];
__device__ int   g_bsums[NB_SCAN];
__device__ float g_dinv[NN];
__device__ int   g_esrc[EE];
__device__ float g_ew[EE];
__device__ int   g_is64;
__device__ __align__(16) float g_Wt[DD * DD];
__device__ __align__(16) float g_h0[(size_t)NN * DD];
__device__ __align__(16) float g_h1[(size_t)NN * DD];

// ---------------- f32x2 helpers ----------------
__device__ __forceinline__ ull ffma2(ull a, ull b, ull c) {
    ull d;
    asm("fma.rn.f32x2 %0, %1, %2, %3;" : "=l"(d) : "l"(a), "l"(b), "l"(c));
    return d;
}
__device__ __forceinline__ ull dupf(float x) {
    ull d; asm("mov.b64 %0, {%1, %1};" : "=l"(d) : "f"(x)); return d;
}
__device__ __forceinline__ float2 ull2f2(ull v) {
    float2 r; asm("mov.b64 {%0, %1}, %2;" : "=f"(r.x), "=f"(r.y) : "l"(v)); return r;
}

// ---------------- dtype detect + zero counts (fused) ----------------
__global__ void k_detect_zero(const unsigned* __restrict__ ei_words,
                              int* __restrict__ flag,
                              int* __restrict__ counts) {
    int i = blockIdx.x * blockDim.x + threadIdx.x;
    if (i < NN) counts[i] = 0;
    if (blockIdx.x == 0) {
        __shared__ int zc;
        if (threadIdx.x == 0) zc = 0;
        __syncthreads();
        int z = 0;
        for (int j = threadIdx.x; j < 1024; j += blockDim.x)
            if (ei_words[2 * j + 1] == 0u) z++;
        atomicAdd(&zc, z);
        __syncthreads();
        if (threadIdx.x == 0) *flag = (zc >= 1000) ? 1 : 0;
    }
}

__device__ __forceinline__ int load_idx(const void* ei, int is64, ll pos) {
    if (is64) return (int)((const ll*)ei)[pos];
    return ((const int*)ei)[pos];
}

// ---------------- degree / CSR construction ----------------

__global__ void k_count(const void* __restrict__ ei, const int* __restrict__ flag,
                        int* __restrict__ counts) {
    int e = blockIdx.x * blockDim.x + threadIdx.x;
    if (e < EE) {
        int is64 = *flag;
        int dst = load_idx(ei, is64, (ll)EE + e);
        if ((unsigned)dst < (unsigned)NN) atomicAdd(&counts[dst], 1);
    }
}

__global__ void k_scan1(const int* __restrict__ counts,
                        int* __restrict__ rowptr,
                        int* __restrict__ bsums) {
    __shared__ int wsums[9];
    int t = threadIdx.x;
    int base = blockIdx.x * 1024 + t * 4;
    int v0 = 0, v1 = 0, v2 = 0, v3 = 0;
    if (base + 0 < NN) v0 = counts[base + 0];
    if (base + 1 < NN) v1 = counts[base + 1];
    if (base + 2 < NN) v2 = counts[base + 2];
    if (base + 3 < NN) v3 = counts[base + 3];
    int loc = v0 + v1 + v2 + v3;

    int lane = t & 31, w = t >> 5;
    int s = loc;
    #pragma unroll
    for (int d = 1; d < 32; d <<= 1) {
        int n = __shfl_up_sync(0xffffffffu, s, d);
        if (lane >= d) s += n;
    }
    if (lane == 31) wsums[w] = s;
    __syncthreads();
    if (t == 0) {
        int acc = 0;
        #pragma unroll
        for (int j = 0; j < 8; j++) { int x = wsums[j]; wsums[j] = acc; acc += x; }
        wsums[8] = acc;
    }
    __syncthreads();
    int excl = s - loc + wsums[w];
    if (base + 0 < NN) { rowptr[base + 0] = excl; excl += v0; }
    if (base + 1 < NN) { rowptr[base + 1] = excl; excl += v1; }
    if (base + 2 < NN) { rowptr[base + 2] = excl; excl += v2; }
    if (base + 3 < NN) { rowptr[base + 3] = excl; excl += v3; }
    if (t == 0) bsums[blockIdx.x] = wsums[8];
}

// warp-parallel scan over NB_SCAN block sums
__global__ void k_scan2(int* __restrict__ bsums, int* __restrict__ rowptr) {
    int lane = threadIdx.x & 31;
    int carry = 0;
    for (int base = 0; base < NB_SCAN; base += 32) {
        int v = (base + lane < NB_SCAN) ? bsums[base + lane] : 0;
        int sIncl = v;
        #pragma unroll
        for (int d = 1; d < 32; d <<= 1) {
            int n = __shfl_up_sync(0xffffffffu, sIncl, d);
            if (lane >= d) sIncl += n;
        }
        if (base + lane < NB_SCAN) bsums[base + lane] = carry + sIncl - v;
        carry += __shfl_sync(0xffffffffu, sIncl, 31);
    }
    if (lane == 0) rowptr[NN] = carry;
}

__global__ void k_scan3(const int* __restrict__ counts,
                        int* __restrict__ rowptr,
                        const int* __restrict__ bsums,
                        int* __restrict__ cursor,
                        float* __restrict__ dinv) {
    int i = blockIdx.x * blockDim.x + threadIdx.x;
    if (i < NN) {
        int r = rowptr[i] + bsums[i >> 10];
        rowptr[i] = r;
        cursor[i] = r;
        dinv[i]   = rsqrtf((float)(counts[i] + 1));   // +1 self-loop
    }
}

__global__ void k_fill(const void* __restrict__ ei, const int* __restrict__ flag,
                       int* __restrict__ cursor,
                       const float* __restrict__ dinv,
                       int* __restrict__ esrc,
                       float* __restrict__ ew) {
    int e = blockIdx.x * blockDim.x + threadIdx.x;
    if (e < EE) {
        int is64 = *flag;
        int s = load_idx(ei, is64, (ll)e);
        int d = load_idx(ei, is64, (ll)EE + e);
        if ((unsigned)s < (unsigned)NN && (unsigned)d < (unsigned)NN) {
            int pos = atomicAdd(&cursor[d], 1);
            if ((unsigned)pos < (unsigned)EE) {
                esrc[pos] = s;
                ew[pos]   = dinv[s] * dinv[d];
            }
        }
    }
}

// ---------------- W transpose ----------------
__global__ void k_wt(const float* __restrict__ W, float* __restrict__ Wt) {
    int i = blockIdx.x * blockDim.x + threadIdx.x;
    if (i < DD * DD) {
        int k = i & (DD - 1);
        int c = i >> 7;
        Wt[k * DD + c] = W[c * DD + k];
    }
}

// ---------------- dense: H0 = X @ W^T  (FFMA2 / f32x2) ----------------
__global__ void k_gemm(const float* __restrict__ X,
                       const float* __restrict__ Wt,
                       float* __restrict__ H0) {
    __shared__ __align__(16) ull   hsT2[32][66];
    __shared__ __align__(16) float Ws[32][132];
    int t  = threadIdx.x;
    int nb = blockIdx.x * 64;
    int tx = t & 31;
    int ty = t >> 5;
    ull acc[8][2] = {};

    for (int kt = 0; kt < DD; kt += 32) {
        #pragma unroll
        for (int r = 0; r < 2; r++) {
            int u   = t + 256 * r;
            int row = u >> 3;
            int kq  = (u & 7) * 4;
            int gr  = nb + row; if (gr >= NN) gr = NN - 1;
            float4 v = *(const float4*)(X + (size_t)gr * DD + kt + kq);
            hsT2[kq + 0][row] = dupf(v.x);
            hsT2[kq + 1][row] = dupf(v.y);
            hsT2[kq + 2][row] = dupf(v.z);
            hsT2[kq + 3][row] = dupf(v.w);
        }
        #pragma unroll
        for (int r = 0; r < 4; r++) {
            int u  = t + 256 * r;
            int k  = u >> 5;
            int cq = (u & 31) * 4;
            float4 v = *(const float4*)(Wt + (size_t)(kt + k) * DD + cq);
            *(float4*)&Ws[k][cq] = v;
        }
        __syncthreads();
        #pragma unroll 8
        for (int k = 0; k < 32; k++) {
            ulonglong2 b01 = *(const ulonglong2*)&Ws[k][tx * 4];
            const ulonglong2* ap = (const ulonglong2*)&hsT2[k][ty * 8];
            #pragma unroll
            for (int q = 0; q < 4; q++) {
                ulonglong2 a2 = ap[q];
                acc[2*q  ][0] = ffma2(a2.x, b01.x, acc[2*q  ][0]);
                acc[2*q  ][1] = ffma2(a2.x, b01.y, acc[2*q  ][1]);
                acc[2*q+1][0] = ffma2(a2.y, b01.x, acc[2*q+1][0]);
                acc[2*q+1][1] = ffma2(a2.y, b01.y, acc[2*q+1][1]);
            }
        }
        __syncthreads();
    }
    #pragma unroll
    for (int j = 0; j < 8; j++) {
        int gr = nb + ty * 8 + j;
        if (gr < NN) {
            float2 p0 = ull2f2(acc[j][0]);
            float2 p1 = ull2f2(acc[j][1]);
            float4 o = make_float4(p0.x, p0.y, p1.x, p1.y);
            *(float4*)(H0 + (size_t)gr * DD + tx * 4) = o;
        }
    }
}

// ---------------- sparse hop: one warp per node ----------------
__global__ void k_hop(const float* __restrict__ hin,
                      float* __restrict__ hout,
                      const int* __restrict__ rowptr,
                      const float* __restrict__ dinv,
                      const int* __restrict__ esrc,
                      const float* __restrict__ ew,
                      const float* __restrict__ bias) {
    int warp = (blockIdx.x * blockDim.x + threadIdx.x) >> 5;
    int lane = threadIdx.x & 31;
    if (warp >= NN) return;
    int i = warp;

    int start = rowptr[i];
    int end   = rowptr[i + 1];
    float di  = dinv[i];
    float sw  = di * di;

    float4 hv = *(const float4*)(hin + (size_t)i * DD + lane * 4);
    float4 acc;
    acc.x = sw * hv.x; acc.y = sw * hv.y; acc.z = sw * hv.z; acc.w = sw * hv.w;

    for (int eb = start; eb < end; eb += 32) {
        int e = eb + lane;
        int s = 0; float w = 0.f;
        if (e < end) { s = esrc[e]; w = ew[e]; }
        int cnt = min(32, end - eb);
        int j = 0;
        for (; j + 2 <= cnt; j += 2) {
            int   s0 = __shfl_sync(0xffffffffu, s, j);
            int   s1 = __shfl_sync(0xffffffffu, s, j + 1);
            float w0 = __shfl_sync(0xffffffffu, w, j);
            float w1 = __shfl_sync(0xffffffffu, w, j + 1);
            float4 v0 = *(const float4*)(hin + (size_t)s0 * DD + lane * 4);
            float4 v1 = *(const float4*)(hin + (size_t)s1 * DD + lane * 4);
            acc.x += w0 * v0.x + w1 * v1.x;
            acc.y += w0 * v0.y + w1 * v1.y;
            acc.z += w0 * v0.z + w1 * v1.z;
            acc.w += w0 * v0.w + w1 * v1.w;
        }
        if (j < cnt) {
            int   sj = __shfl_sync(0xffffffffu, s, j);
            float wj = __shfl_sync(0xffffffffu, w, j);
            float4 v = *(const float4*)(hin + (size_t)sj * DD + lane * 4);
            acc.x += wj * v.x; acc.y += wj * v.y; acc.z += wj * v.z; acc.w += wj * v.w;
        }
    }
    if (bias != nullptr) {
        float4 b4 = *(const float4*)(bias + lane * 4);
        acc.x += b4.x; acc.y += b4.y; acc.z += b4.z; acc.w += b4.w;
    }
    *(float4*)(hout + (size_t)i * DD + lane * 4) = acc;
}

// ---------------- launch ----------------
extern "C" void kernel_launch(void* const* d_in, const int* in_sizes, int n_in,
                              void* d_out, int out_size) {
    const float* x  = (const float*)d_in[0];
    const void*  ei = (const void*)d_in[1];
    const float* W  = (const float*)d_in[2];
    const float* b  = (const float*)d_in[3];
    for (int i = 0; i < n_in; i++) {
        switch (in_sizes[i]) {
            case NN * DD:   x  = (const float*)d_in[i]; break;
            case 2 * EE:    ei = (const void*)d_in[i];  break;
            case DD * DD:   W  = (const float*)d_in[i]; break;
            case DD:        b  = (const float*)d_in[i]; break;
            default: break;
        }
    }
    float* out = (float*)d_out;
    (void)out_size;

    void *p_counts, *p_rowptr, *p_cursor, *p_bsums, *p_dinv, *p_esrc, *p_ew,
         *p_h0, *p_h1, *p_is64, *p_wt;
    cudaGetSymbolAddress(&p_counts, g_counts);
    cudaGetSymbolAddress(&p_rowptr, g_rowptr);
    cudaGetSymbolAddress(&p_cursor, g_cursor);
    cudaGetSymbolAddress(&p_bsums,  g_bsums);
    cudaGetSymbolAddress(&p_dinv,   g_dinv);
    cudaGetSymbolAddress(&p_esrc,   g_esrc);
    cudaGetSymbolAddress(&p_ew,     g_ew);
    cudaGetSymbolAddress(&p_h0,     g_h0);
    cudaGetSymbolAddress(&p_h1,     g_h1);
    cudaGetSymbolAddress(&p_is64,   g_is64);
    cudaGetSymbolAddress(&p_wt,     g_Wt);
    int*   counts = (int*)p_counts;
    int*   rowptr = (int*)p_rowptr;
    int*   cursor = (int*)p_cursor;
    int*   bsums  = (int*)p_bsums;
    float* dinv   = (float*)p_dinv;
    int*   esrc   = (int*)p_esrc;
    float* ew     = (float*)p_ew;
    float* h0     = (float*)p_h0;
    float* h1     = (float*)p_h1;
    int*   is64   = (int*)p_is64;
    float* wt     = (float*)p_wt;

    // One-time side-stream/event creation (first call is the uncaptured
    // correctness run; replays see identical enqueue structure every call).
    static cudaStream_t s_side = nullptr;
    static cudaEvent_t  s_fork = nullptr, s_join = nullptr;
    if (s_side == nullptr) {
        cudaStreamCreateWithFlags(&s_side, cudaStreamNonBlocking);
        cudaEventCreateWithFlags(&s_fork, cudaEventDisableTiming);
        cudaEventCreateWithFlags(&s_join, cudaEventDisableTiming);
    }

    // Fork: dense chain (wt -> gemm) runs concurrently with CSR build.
    cudaEventRecord(s_fork, 0);
    cudaStreamWaitEvent(s_side, s_fork, 0);
    k_wt  <<<(DD * DD + 255) / 256, 256, 0, s_side>>>(W, wt);
    k_gemm<<<(NN + 63) / 64,     256, 0, s_side>>>(x, wt, h0);   // h0 = X W^T
    cudaEventRecord(s_join, s_side);

    // CSR build on the main (legacy) stream.
    k_detect_zero<<<(NN + 255) / 256, 256>>>((const unsigned*)ei, is64, counts);
    k_count<<<(EE + 255) / 256, 256>>>(ei, is64, counts);
    k_scan1<<<NB_SCAN, 256>>>(counts, rowptr, bsums);
    k_scan2<<<1, 32>>>(bsums, rowptr);
    k_scan3<<<(NN + 255) / 256, 256>>>(counts, rowptr, bsums, cursor, dinv);
    k_fill <<<(EE + 255) / 256, 256>>>(ei, is64, cursor, dinv, esrc, ew);

    // Join: hops need both h0 (dense chain) and the CSR.
    cudaStreamWaitEvent(0, s_join, 0);

    const int hop_blocks = (NN * 32 + 255) / 256;
    k_hop<<<hop_blocks, 256>>>(h0, h1, rowptr, dinv, esrc, ew, nullptr);  // hop 1
    k_hop<<<hop_blocks, 256>>>(h1, h0, rowptr, dinv, esrc, ew, nullptr);  // hop 2
    k_hop<<<hop_blocks, 256>>>(h0, out, rowptr, dinv, esrc, ew, b);       // hop 3 (+bias)
}

// round 12
// speedup vs baseline: 1.4122x; 1.2805x over previous
#include <cuda_runtime.h>
#include <cuda_fp16.h>

#define NN 100000
#define EE 800000
#define DD 128
#define NB_SCAN ((NN + 1023) / 1024)

typedef long long ll;
typedef unsigned long long ull;

// ---------------- scratch (device globals; no runtime allocation) ----------------
__device__ int    g_counts[NN];
__device__ int    g_rowptr[NN + 1];
__device__ int    g_cursor[NN];
__device__ int    g_bsums[NB_SCAN];
__device__ float  g_dinv[NN];
__device__ int    g_esrc[EE];
__device__ float  g_ew[EE];
__device__ int    g_is64;
__device__ __align__(16) float  g_Wt[DD * DD];
__device__ __align__(16) __half g_ha[(size_t)NN * DD];   // fp16 h ping
__device__ __align__(16) __half g_hb[(size_t)NN * DD];   // fp16 h pong

// ---------------- f32x2 helpers ----------------
__device__ __forceinline__ ull ffma2(ull a, ull b, ull c) {
    ull d;
    asm("fma.rn.f32x2 %0, %1, %2, %3;" : "=l"(d) : "l"(a), "l"(b), "l"(c));
    return d;
}
__device__ __forceinline__ ull dupf(float x) {
    ull d; asm("mov.b64 %0, {%1, %1};" : "=l"(d) : "f"(x)); return d;
}
__device__ __forceinline__ float2 ull2f2(ull v) {
    float2 r; asm("mov.b64 {%0, %1}, %2;" : "=f"(r.x), "=f"(r.y) : "l"(v)); return r;
}

// ---------------- dtype detect + zero counts (fused) ----------------
__global__ void k_detect_zero(const unsigned* __restrict__ ei_words,
                              int* __restrict__ flag,
                              int* __restrict__ counts) {
    int i = blockIdx.x * blockDim.x + threadIdx.x;
    if (i < NN) counts[i] = 0;
    if (blockIdx.x == 0) {
        __shared__ int zc;
        if (threadIdx.x == 0) zc = 0;
        __syncthreads();
        int z = 0;
        for (int j = threadIdx.x; j < 1024; j += blockDim.x)
            if (ei_words[2 * j + 1] == 0u) z++;
        atomicAdd(&zc, z);
        __syncthreads();
        if (threadIdx.x == 0) *flag = (zc >= 1000) ? 1 : 0;
    }
}

__device__ __forceinline__ int load_idx(const void* ei, int is64, ll pos) {
    if (is64) return (int)((const ll*)ei)[pos];
    return ((const int*)ei)[pos];
}

// ---------------- degree / CSR construction ----------------

__global__ void k_count(const void* __restrict__ ei, const int* __restrict__ flag,
                        int* __restrict__ counts) {
    int e = blockIdx.x * blockDim.x + threadIdx.x;
    if (e < EE) {
        int is64 = *flag;
        int dst = load_idx(ei, is64, (ll)EE + e);
        if ((unsigned)dst < (unsigned)NN) atomicAdd(&counts[dst], 1);
    }
}

__global__ void k_scan1(const int* __restrict__ counts,
                        int* __restrict__ rowptr,
                        int* __restrict__ bsums) {
    __shared__ int wsums[9];
    int t = threadIdx.x;
    int base = blockIdx.x * 1024 + t * 4;
    int v0 = 0, v1 = 0, v2 = 0, v3 = 0;
    if (base + 0 < NN) v0 = counts[base + 0];
    if (base + 1 < NN) v1 = counts[base + 1];
    if (base + 2 < NN) v2 = counts[base + 2];
    if (base + 3 < NN) v3 = counts[base + 3];
    int loc = v0 + v1 + v2 + v3;

    int lane = t & 31, w = t >> 5;
    int s = loc;
    #pragma unroll
    for (int d = 1; d < 32; d <<= 1) {
        int n = __shfl_up_sync(0xffffffffu, s, d);
        if (lane >= d) s += n;
    }
    if (lane == 31) wsums[w] = s;
    __syncthreads();
    if (t == 0) {
        int acc = 0;
        #pragma unroll
        for (int j = 0; j < 8; j++) { int x = wsums[j]; wsums[j] = acc; acc += x; }
        wsums[8] = acc;
    }
    __syncthreads();
    int excl = s - loc + wsums[w];
    if (base + 0 < NN) { rowptr[base + 0] = excl; excl += v0; }
    if (base + 1 < NN) { rowptr[base + 1] = excl; excl += v1; }
    if (base + 2 < NN) { rowptr[base + 2] = excl; excl += v2; }
    if (base + 3 < NN) { rowptr[base + 3] = excl; excl += v3; }
    if (t == 0) bsums[blockIdx.x] = wsums[8];
}

__global__ void k_scan2(int* __restrict__ bsums, int* __restrict__ rowptr) {
    int lane = threadIdx.x & 31;
    int carry = 0;
    for (int base = 0; base < NB_SCAN; base += 32) {
        int v = (base + lane < NB_SCAN) ? bsums[base + lane] : 0;
        int sIncl = v;
        #pragma unroll
        for (int d = 1; d < 32; d <<= 1) {
            int n = __shfl_up_sync(0xffffffffu, sIncl, d);
            if (lane >= d) sIncl += n;
        }
        if (base + lane < NB_SCAN) bsums[base + lane] = carry + sIncl - v;
        carry += __shfl_sync(0xffffffffu, sIncl, 31);
    }
    if (lane == 0) rowptr[NN] = carry;
}

__global__ void k_scan3(const int* __restrict__ counts,
                        int* __restrict__ rowptr,
                        const int* __restrict__ bsums,
                        int* __restrict__ cursor,
                        float* __restrict__ dinv) {
    int i = blockIdx.x * blockDim.x + threadIdx.x;
    if (i < NN) {
        int r = rowptr[i] + bsums[i >> 10];
        rowptr[i] = r;
        cursor[i] = r;
        dinv[i]   = rsqrtf((float)(counts[i] + 1));   // +1 self-loop
    }
}

__global__ void k_fill(const void* __restrict__ ei, const int* __restrict__ flag,
                       int* __restrict__ cursor,
                       const float* __restrict__ dinv,
                       int* __restrict__ esrc,
                       float* __restrict__ ew) {
    int e = blockIdx.x * blockDim.x + threadIdx.x;
    if (e < EE) {
        int is64 = *flag;
        int s = load_idx(ei, is64, (ll)e);
        int d = load_idx(ei, is64, (ll)EE + e);
        if ((unsigned)s < (unsigned)NN && (unsigned)d < (unsigned)NN) {
            int pos = atomicAdd(&cursor[d], 1);
            if ((unsigned)pos < (unsigned)EE) {
                esrc[pos] = s;
                ew[pos]   = dinv[s] * dinv[d];
            }
        }
    }
}

// ---------------- W transpose ----------------
__global__ void k_wt(const float* __restrict__ W, float* __restrict__ Wt) {
    int i = blockIdx.x * blockDim.x + threadIdx.x;
    if (i < DD * DD) {
        int k = i & (DD - 1);
        int c = i >> 7;
        Wt[k * DD + c] = W[c * DD + k];
    }
}

// ---------------- dense: H0 = X @ W^T  (FFMA2, fp16 output) ----------------
__global__ void k_gemm(const float* __restrict__ X,
                       const float* __restrict__ Wt,
                       __half* __restrict__ H0) {
    __shared__ __align__(16) ull   hsT2[32][66];
    __shared__ __align__(16) float Ws[32][132];
    int t  = threadIdx.x;
    int nb = blockIdx.x * 64;
    int tx = t & 31;
    int ty = t >> 5;
    ull acc[8][2] = {};

    for (int kt = 0; kt < DD; kt += 32) {
        #pragma unroll
        for (int r = 0; r < 2; r++) {
            int u   = t + 256 * r;
            int row = u >> 3;
            int kq  = (u & 7) * 4;
            int gr  = nb + row; if (gr >= NN) gr = NN - 1;
            float4 v = *(const float4*)(X + (size_t)gr * DD + kt + kq);
            hsT2[kq + 0][row] = dupf(v.x);
            hsT2[kq + 1][row] = dupf(v.y);
            hsT2[kq + 2][row] = dupf(v.z);
            hsT2[kq + 3][row] = dupf(v.w);
        }
        #pragma unroll
        for (int r = 0; r < 4; r++) {
            int u  = t + 256 * r;
            int k  = u >> 5;
            int cq = (u & 31) * 4;
            float4 v = *(const float4*)(Wt + (size_t)(kt + k) * DD + cq);
            *(float4*)&Ws[k][cq] = v;
        }
        __syncthreads();
        #pragma unroll 8
        for (int k = 0; k < 32; k++) {
            ulonglong2 b01 = *(const ulonglong2*)&Ws[k][tx * 4];
            const ulonglong2* ap = (const ulonglong2*)&hsT2[k][ty * 8];
            #pragma unroll
            for (int q = 0; q < 4; q++) {
                ulonglong2 a2 = ap[q];
                acc[2*q  ][0] = ffma2(a2.x, b01.x, acc[2*q  ][0]);
                acc[2*q  ][1] = ffma2(a2.x, b01.y, acc[2*q  ][1]);
                acc[2*q+1][0] = ffma2(a2.y, b01.x, acc[2*q+1][0]);
                acc[2*q+1][1] = ffma2(a2.y, b01.y, acc[2*q+1][1]);
            }
        }
        __syncthreads();
    }
    #pragma unroll
    for (int j = 0; j < 8; j++) {
        int gr = nb + ty * 8 + j;
        if (gr < NN) {
            float2 p0 = ull2f2(acc[j][0]);
            float2 p1 = ull2f2(acc[j][1]);
            __half2 h01 = __floats2half2_rn(p0.x, p0.y);
            __half2 h23 = __floats2half2_rn(p1.x, p1.y);
            uint2 st;
            st.x = *(unsigned*)&h01;
            st.y = *(unsigned*)&h23;
            ((uint2*)(H0 + (size_t)gr * DD))[tx] = st;
        }
    }
}

// ---------------- sparse hop: one warp per node, fp16 gather, fp32 accumulate ----------------
// FINAL=false: write fp16 to hout16. FINAL=true: write fp32 (+bias) to outf.
template <bool FINAL>
__global__ void k_hop(const __half* __restrict__ hin,
                      __half* __restrict__ hout16,
                      float* __restrict__ outf,
                      const int* __restrict__ rowptr,
                      const float* __restrict__ dinv,
                      const int* __restrict__ esrc,
                      const float* __restrict__ ew,
                      const float* __restrict__ bias) {
    int warp = (blockIdx.x * blockDim.x + threadIdx.x) >> 5;
    int lane = threadIdx.x & 31;
    if (warp >= NN) return;
    int i = warp;

    int start = rowptr[i];
    int end   = rowptr[i + 1];
    float di  = dinv[i];
    float sw  = di * di;

    // self term (4 features per lane: cols lane*4 .. lane*4+3)
    uint2 su = ((const uint2*)(hin + (size_t)i * DD))[lane];
    float2 f01 = __half22float2(*(__half2*)&su.x);
    float2 f23 = __half22float2(*(__half2*)&su.y);
    float4 acc;
    acc.x = sw * f01.x; acc.y = sw * f01.y; acc.z = sw * f23.x; acc.w = sw * f23.y;

    for (int eb = start; eb < end; eb += 32) {
        int e = eb + lane;
        int s = 0; float w = 0.f;
        if (e < end) { s = esrc[e]; w = ew[e]; }
        int cnt = min(32, end - eb);
        int j = 0;
        for (; j + 2 <= cnt; j += 2) {
            int   s0 = __shfl_sync(0xffffffffu, s, j);
            int   s1 = __shfl_sync(0xffffffffu, s, j + 1);
            float w0 = __shfl_sync(0xffffffffu, w, j);
            float w1 = __shfl_sync(0xffffffffu, w, j + 1);
            uint2 u0 = ((const uint2*)(hin + (size_t)s0 * DD))[lane];
            uint2 u1 = ((const uint2*)(hin + (size_t)s1 * DD))[lane];
            float2 a01 = __half22float2(*(__half2*)&u0.x);
            float2 a23 = __half22float2(*(__half2*)&u0.y);
            float2 b01 = __half22float2(*(__half2*)&u1.x);
            float2 b23 = __half22float2(*(__half2*)&u1.y);
            acc.x += w0 * a01.x + w1 * b01.x;
            acc.y += w0 * a01.y + w1 * b01.y;
            acc.z += w0 * a23.x + w1 * b23.x;
            acc.w += w0 * a23.y + w1 * b23.y;
        }
        if (j < cnt) {
            int   sj = __shfl_sync(0xffffffffu, s, j);
            float wj = __shfl_sync(0xffffffffu, w, j);
            uint2 u0 = ((const uint2*)(hin + (size_t)sj * DD))[lane];
            float2 a01 = __half22float2(*(__half2*)&u0.x);
            float2 a23 = __half22float2(*(__half2*)&u0.y);
            acc.x += wj * a01.x; acc.y += wj * a01.y;
            acc.z += wj * a23.x; acc.w += wj * a23.y;
        }
    }

    if (FINAL) {
        float4 b4 = *(const float4*)(bias + lane * 4);
        acc.x += b4.x; acc.y += b4.y; acc.z += b4.z; acc.w += b4.w;
        *(float4*)(outf + (size_t)i * DD + lane * 4) = acc;
    } else {
        __half2 h01 = __floats2half2_rn(acc.x, acc.y);
        __half2 h23 = __floats2half2_rn(acc.z, acc.w);
        uint2 st;
        st.x = *(unsigned*)&h01;
        st.y = *(unsigned*)&h23;
        ((uint2*)(hout16 + (size_t)i * DD))[lane] = st;
    }
}

// ---------------- launch ----------------
extern "C" void kernel_launch(void* const* d_in, const int* in_sizes, int n_in,
                              void* d_out, int out_size) {
    const float* x  = (const float*)d_in[0];
    const void*  ei = (const void*)d_in[1];
    const float* W  = (const float*)d_in[2];
    const float* b  = (const float*)d_in[3];
    for (int i = 0; i < n_in; i++) {
        switch (in_sizes[i]) {
            case NN * DD:   x  = (const float*)d_in[i]; break;
            case 2 * EE:    ei = (const void*)d_in[i];  break;
            case DD * DD:   W  = (const float*)d_in[i]; break;
            case DD:        b  = (const float*)d_in[i]; break;
            default: break;
        }
    }
    float* out = (float*)d_out;
    (void)out_size;

    void *p_counts, *p_rowptr, *p_cursor, *p_bsums, *p_dinv, *p_esrc, *p_ew,
         *p_ha, *p_hb, *p_is64, *p_wt;
    cudaGetSymbolAddress(&p_counts, g_counts);
    cudaGetSymbolAddress(&p_rowptr, g_rowptr);
    cudaGetSymbolAddress(&p_cursor, g_cursor);
    cudaGetSymbolAddress(&p_bsums,  g_bsums);
    cudaGetSymbolAddress(&p_dinv,   g_dinv);
    cudaGetSymbolAddress(&p_esrc,   g_esrc);
    cudaGetSymbolAddress(&p_ew,     g_ew);
    cudaGetSymbolAddress(&p_ha,     g_ha);
    cudaGetSymbolAddress(&p_hb,     g_hb);
    cudaGetSymbolAddress(&p_is64,   g_is64);
    cudaGetSymbolAddress(&p_wt,     g_Wt);
    int*    counts = (int*)p_counts;
    int*    rowptr = (int*)p_rowptr;
    int*    cursor = (int*)p_cursor;
    int*    bsums  = (int*)p_bsums;
    float*  dinv   = (float*)p_dinv;
    int*    esrc   = (int*)p_esrc;
    float*  ew     = (float*)p_ew;
    __half* ha     = (__half*)p_ha;
    __half* hb     = (__half*)p_hb;
    int*    is64   = (int*)p_is64;
    float*  wt     = (float*)p_wt;

    static cudaStream_t s_side = nullptr;
    static cudaEvent_t  s_fork = nullptr, s_join = nullptr;
    if (s_side == nullptr) {
        cudaStreamCreateWithFlags(&s_side, cudaStreamNonBlocking);
        cudaEventCreateWithFlags(&s_fork, cudaEventDisableTiming);
        cudaEventCreateWithFlags(&s_join, cudaEventDisableTiming);
    }

    // Fork: dense chain (wt -> gemm) runs concurrently with CSR build.
    cudaEventRecord(s_fork, 0);
    cudaStreamWaitEvent(s_side, s_fork, 0);
    k_wt  <<<(DD * DD + 255) / 256, 256, 0, s_side>>>(W, wt);
    k_gemm<<<(NN + 63) / 64,     256, 0, s_side>>>(x, wt, ha);   // ha = fp16(X W^T)
    cudaEventRecord(s_join, s_side);

    // CSR build on the main (legacy) stream.
    k_detect_zero<<<(NN + 255) / 256, 256>>>((const unsigned*)ei, is64, counts);
    k_count<<<(EE + 255) / 256, 256>>>(ei, is64, counts);
    k_scan1<<<NB_SCAN, 256>>>(counts, rowptr, bsums);
    k_scan2<<<1, 32>>>(bsums, rowptr);
    k_scan3<<<(NN + 255) / 256, 256>>>(counts, rowptr, bsums, cursor, dinv);
    k_fill <<<(EE + 255) / 256, 256>>>(ei, is64, cursor, dinv, esrc, ew);

    cudaStreamWaitEvent(0, s_join, 0);

    const int hop_blocks = (NN * 32 + 255) / 256;
    k_hop<false><<<hop_blocks, 256>>>(ha, hb, nullptr, rowptr, dinv, esrc, ew, nullptr);
    k_hop<false><<<hop_blocks, 256>>>(hb, ha, nullptr, rowptr, dinv, esrc, ew, nullptr);
    k_hop<true> <<<hop_blocks, 256>>>(ha, nullptr, out, rowptr, dinv, esrc, ew, b);
}

// round 13
// speedup vs baseline: 1.9000x; 1.3454x over previous
#include <cuda_runtime.h>
#include <cuda_fp16.h>

#define NN 100000
#define EE 800000
#define DD 128
#define NB_SCAN ((NN + 1023) / 1024)
#define GEMM_M 64

typedef long long ll;
typedef unsigned long long ull;

// ---------------- scratch (device globals; no runtime allocation) ----------------
__device__ int    g_counts[NN];
__device__ int    g_rowptr[NN + 1];
__device__ int    g_cursor[NN];
__device__ int    g_bsums[NB_SCAN];
__device__ float  g_dinv[NN];
__device__ int    g_esrc[EE];
__device__ float  g_ew[EE];
__device__ int    g_is64;
__device__ __align__(16) __half g_Wh[DD * DD];           // fp16 W, [n][k] row-major
__device__ __align__(16) __half g_ha[(size_t)NN * DD];   // fp16 h ping
__device__ __align__(16) __half g_hb[(size_t)NN * DD];   // fp16 h pong

// ---------------- dtype detect + zero counts (fused) ----------------
__global__ void k_detect_zero(const unsigned* __restrict__ ei_words,
                              int* __restrict__ flag,
                              int* __restrict__ counts) {
    int i = blockIdx.x * blockDim.x + threadIdx.x;
    if (i < NN) counts[i] = 0;
    if (blockIdx.x == 0) {
        __shared__ int zc;
        if (threadIdx.x == 0) zc = 0;
        __syncthreads();
        int z = 0;
        for (int j = threadIdx.x; j < 1024; j += blockDim.x)
            if (ei_words[2 * j + 1] == 0u) z++;
        atomicAdd(&zc, z);
        __syncthreads();
        if (threadIdx.x == 0) *flag = (zc >= 1000) ? 1 : 0;
    }
}

__device__ __forceinline__ int load_idx(const void* ei, int is64, ll pos) {
    if (is64) return (int)((const ll*)ei)[pos];
    return ((const int*)ei)[pos];
}

// ---------------- degree / CSR construction ----------------

__global__ void k_count(const void* __restrict__ ei, const int* __restrict__ flag,
                        int* __restrict__ counts) {
    int e = blockIdx.x * blockDim.x + threadIdx.x;
    if (e < EE) {
        int is64 = *flag;
        int dst = load_idx(ei, is64, (ll)EE + e);
        if ((unsigned)dst < (unsigned)NN) atomicAdd(&counts[dst], 1);
    }
}

__global__ void k_scan1(const int* __restrict__ counts,
                        int* __restrict__ rowptr,
                        int* __restrict__ bsums) {
    __shared__ int wsums[9];
    int t = threadIdx.x;
    int base = blockIdx.x * 1024 + t * 4;
    int v0 = 0, v1 = 0, v2 = 0, v3 = 0;
    if (base + 0 < NN) v0 = counts[base + 0];
    if (base + 1 < NN) v1 = counts[base + 1];
    if (base + 2 < NN) v2 = counts[base + 2];
    if (base + 3 < NN) v3 = counts[base + 3];
    int loc = v0 + v1 + v2 + v3;

    int lane = t & 31, w = t >> 5;
    int s = loc;
    #pragma unroll
    for (int d = 1; d < 32; d <<= 1) {
        int n = __shfl_up_sync(0xffffffffu, s, d);
        if (lane >= d) s += n;
    }
    if (lane == 31) wsums[w] = s;
    __syncthreads();
    if (t == 0) {
        int acc = 0;
        #pragma unroll
        for (int j = 0; j < 8; j++) { int x = wsums[j]; wsums[j] = acc; acc += x; }
        wsums[8] = acc;
    }
    __syncthreads();
    int excl = s - loc + wsums[w];
    if (base + 0 < NN) { rowptr[base + 0] = excl; excl += v0; }
    if (base + 1 < NN) { rowptr[base + 1] = excl; excl += v1; }
    if (base + 2 < NN) { rowptr[base + 2] = excl; excl += v2; }
    if (base + 3 < NN) { rowptr[base + 3] = excl; excl += v3; }
    if (t == 0) bsums[blockIdx.x] = wsums[8];
}

__global__ void k_scan2(int* __restrict__ bsums, int* __restrict__ rowptr) {
    int lane = threadIdx.x & 31;
    int carry = 0;
    for (int base = 0; base < NB_SCAN; base += 32) {
        int v = (base + lane < NB_SCAN) ? bsums[base + lane] : 0;
        int sIncl = v;
        #pragma unroll
        for (int d = 1; d < 32; d <<= 1) {
            int n = __shfl_up_sync(0xffffffffu, sIncl, d);
            if (lane >= d) sIncl += n;
        }
        if (base + lane < NB_SCAN) bsums[base + lane] = carry + sIncl - v;
        carry += __shfl_sync(0xffffffffu, sIncl, 31);
    }
    if (lane == 0) rowptr[NN] = carry;
}

__global__ void k_scan3(const int* __restrict__ counts,
                        int* __restrict__ rowptr,
                        const int* __restrict__ bsums,
                        int* __restrict__ cursor,
                        float* __restrict__ dinv) {
    int i = blockIdx.x * blockDim.x + threadIdx.x;
    if (i < NN) {
        int r = rowptr[i] + bsums[i >> 10];
        rowptr[i] = r;
        cursor[i] = r;
        dinv[i]   = rsqrtf((float)(counts[i] + 1));   // +1 self-loop
    }
}

__global__ void k_fill(const void* __restrict__ ei, const int* __restrict__ flag,
                       int* __restrict__ cursor,
                       const float* __restrict__ dinv,
                       int* __restrict__ esrc,
                       float* __restrict__ ew) {
    int e = blockIdx.x * blockDim.x + threadIdx.x;
    if (e < EE) {
        int is64 = *flag;
        int s = load_idx(ei, is64, (ll)e);
        int d = load_idx(ei, is64, (ll)EE + e);
        if ((unsigned)s < (unsigned)NN && (unsigned)d < (unsigned)NN) {
            int pos = atomicAdd(&cursor[d], 1);
            if ((unsigned)pos < (unsigned)EE) {
                esrc[pos] = s;
                ew[pos]   = dinv[s] * dinv[d];
            }
        }
    }
}

// ---------------- W -> fp16 ----------------
__global__ void k_wh(const float* __restrict__ W, __half* __restrict__ Wh) {
    int i = blockIdx.x * blockDim.x + threadIdx.x;
    if (i < DD * DD) Wh[i] = __float2half(W[i]);
}

// ---------------- tensor-core helpers ----------------
__device__ __forceinline__ void ldsm_x4(unsigned& r0, unsigned& r1, unsigned& r2, unsigned& r3,
                                        unsigned addr) {
    asm volatile("ldmatrix.sync.aligned.m8n8.x4.shared.b16 {%0,%1,%2,%3}, [%4];"
                 : "=r"(r0), "=r"(r1), "=r"(r2), "=r"(r3) : "r"(addr));
}
__device__ __forceinline__ void mma16816(float* d,
                                         unsigned a0, unsigned a1, unsigned a2, unsigned a3,
                                         unsigned b0, unsigned b1) {
    asm volatile("mma.sync.aligned.m16n8k16.row.col.f32.f16.f16.f32 "
                 "{%0,%1,%2,%3}, {%4,%5,%6,%7}, {%8,%9}, {%0,%1,%2,%3};"
                 : "+f"(d[0]), "+f"(d[1]), "+f"(d[2]), "+f"(d[3])
                 : "r"(a0), "r"(a1), "r"(a2), "r"(a3), "r"(b0), "r"(b1));
}

// ---------------- dense: H0 = fp16( X @ W^T ), HMMA ----------------
// CTA: 64 rows x 128 cols, 128 threads (4 warps x 16 rows).
// smem XOR swizzle: 16B chunk c of row r stored at chunk (c ^ (r&7)).
__global__ __launch_bounds__(128) void k_gemm(const float* __restrict__ X,
                                              const __half* __restrict__ Wh,
                                              __half* __restrict__ H0) {
    __shared__ __align__(16) __half As[GEMM_M * DD];   // 16 KB
    __shared__ __align__(16) __half Bs[DD * DD];       // 32 KB
    int t = threadIdx.x;
    int warp = t >> 5, lane = t & 31;
    int m0 = blockIdx.x * GEMM_M;

    // A tile: 64 rows x 16 chunks, fp32 -> fp16
    #pragma unroll
    for (int r = 0; r < 8; r++) {
        int idx = t + 128 * r;          // 0..1023
        int row = idx >> 4, c = idx & 15;
        int gr = m0 + row; if (gr >= NN) gr = NN - 1;
        const float4* src = (const float4*)(X + (size_t)gr * DD + c * 8);
        float4 v0 = src[0], v1 = src[1];
        __half2 h0 = __floats2half2_rn(v0.x, v0.y);
        __half2 h1 = __floats2half2_rn(v0.z, v0.w);
        __half2 h2 = __floats2half2_rn(v1.x, v1.y);
        __half2 h3 = __floats2half2_rn(v1.z, v1.w);
        uint4 st;
        st.x = *(unsigned*)&h0; st.y = *(unsigned*)&h1;
        st.z = *(unsigned*)&h2; st.w = *(unsigned*)&h3;
        int sc = c ^ (row & 7);
        *(uint4*)((char*)As + row * 256 + sc * 16) = st;
    }
    // B tile: 128 rows(n) x 16 chunks from fp16 W
    #pragma unroll
    for (int r = 0; r < 16; r++) {
        int idx = t + 128 * r;          // 0..2047
        int row = idx >> 4, c = idx & 15;
        uint4 v = *(const uint4*)(Wh + (size_t)row * DD + c * 8);
        int sc = c ^ (row & 7);
        *(uint4*)((char*)Bs + row * 256 + sc * 16) = v;
    }
    __syncthreads();

    unsigned As_base = (unsigned)__cvta_generic_to_shared(As);
    unsigned Bs_base = (unsigned)__cvta_generic_to_shared(Bs);
    int grp = lane >> 3, lr = lane & 7;
    int mrow = warp * 16;
    float d[16][4] = {};

    #pragma unroll
    for (int ks = 0; ks < 8; ks++) {
        // A frag: matrices {m0-7 klow, m8-15 klow, m0-7 khigh, m8-15 khigh}
        int arow = mrow + lr + ((grp & 1) ? 8 : 0);
        int achk = 2 * ks + ((grp & 2) ? 1 : 0);
        unsigned aaddr = As_base + arow * 256 + ((achk ^ (arow & 7)) * 16);
        unsigned a0, a1, a2, a3;
        ldsm_x4(a0, a1, a2, a3, aaddr);
        #pragma unroll
        for (int jj = 0; jj < 8; jj++) {
            int nt = jj * 2;
            // B frags: {tile nt klow, tile nt khigh, tile nt+1 klow, tile nt+1 khigh}
            int brow = nt * 8 + lr + ((grp & 2) ? 8 : 0);
            int bchk = 2 * ks + (grp & 1);
            unsigned baddr = Bs_base + brow * 256 + ((bchk ^ (brow & 7)) * 16);
            unsigned b0, b1, b2, b3;
            ldsm_x4(b0, b1, b2, b3, baddr);
            mma16816(d[nt],     a0, a1, a2, a3, b0, b1);
            mma16816(d[nt + 1], a0, a1, a2, a3, b2, b3);
        }
    }

    // epilogue: fp16 store
    int orow = m0 + mrow + (lane >> 2);
    int ocol = 2 * (lane & 3);
    #pragma unroll
    for (int j = 0; j < 16; j++) {
        __half2 lo = __floats2half2_rn(d[j][0], d[j][1]);
        __half2 hi = __floats2half2_rn(d[j][2], d[j][3]);
        if (orow < NN)     *(__half2*)(H0 + (size_t)orow * DD + j * 8 + ocol) = lo;
        if (orow + 8 < NN) *(__half2*)(H0 + (size_t)(orow + 8) * DD + j * 8 + ocol) = hi;
    }
}

// ---------------- sparse hop: one warp per node, fp16 gather, fp32 accumulate ----------------
template <bool FINAL>
__global__ void k_hop(const __half* __restrict__ hin,
                      __half* __restrict__ hout16,
                      float* __restrict__ outf,
                      const int* __restrict__ rowptr,
                      const float* __restrict__ dinv,
                      const int* __restrict__ esrc,
                      const float* __restrict__ ew,
                      const float* __restrict__ bias) {
    int warp = (blockIdx.x * blockDim.x + threadIdx.x) >> 5;
    int lane = threadIdx.x & 31;
    if (warp >= NN) return;
    int i = warp;

    int start = rowptr[i];
    int end   = rowptr[i + 1];
    float di  = dinv[i];
    float sw  = di * di;

    uint2 su = ((const uint2*)(hin + (size_t)i * DD))[lane];
    float2 f01 = __half22float2(*(__half2*)&su.x);
    float2 f23 = __half22float2(*(__half2*)&su.y);
    float4 acc;
    acc.x = sw * f01.x; acc.y = sw * f01.y; acc.z = sw * f23.x; acc.w = sw * f23.y;

    for (int eb = start; eb < end; eb += 32) {
        int e = eb + lane;
        int s = 0; float w = 0.f;
        if (e < end) { s = esrc[e]; w = ew[e]; }
        int cnt = min(32, end - eb);
        int j = 0;
        for (; j + 2 <= cnt; j += 2) {
            int   s0 = __shfl_sync(0xffffffffu, s, j);
            int   s1 = __shfl_sync(0xffffffffu, s, j + 1);
            float w0 = __shfl_sync(0xffffffffu, w, j);
            float w1 = __shfl_sync(0xffffffffu, w, j + 1);
            uint2 u0 = ((const uint2*)(hin + (size_t)s0 * DD))[lane];
            uint2 u1 = ((const uint2*)(hin + (size_t)s1 * DD))[lane];
            float2 a01 = __half22float2(*(__half2*)&u0.x);
            float2 a23 = __half22float2(*(__half2*)&u0.y);
            float2 b01 = __half22float2(*(__half2*)&u1.x);
            float2 b23 = __half22float2(*(__half2*)&u1.y);
            acc.x += w0 * a01.x + w1 * b01.x;
            acc.y += w0 * a01.y + w1 * b01.y;
            acc.z += w0 * a23.x + w1 * b23.x;
            acc.w += w0 * a23.y + w1 * b23.y;
        }
        if (j < cnt) {
            int   sj = __shfl_sync(0xffffffffu, s, j);
            float wj = __shfl_sync(0xffffffffu, w, j);
            uint2 u0 = ((const uint2*)(hin + (size_t)sj * DD))[lane];
            float2 a01 = __half22float2(*(__half2*)&u0.x);
            float2 a23 = __half22float2(*(__half2*)&u0.y);
            acc.x += wj * a01.x; acc.y += wj * a01.y;
            acc.z += wj * a23.x; acc.w += wj * a23.y;
        }
    }

    if (FINAL) {
        float4 b4 = *(const float4*)(bias + lane * 4);
        acc.x += b4.x; acc.y += b4.y; acc.z += b4.z; acc.w += b4.w;
        *(float4*)(outf + (size_t)i * DD + lane * 4) = acc;
    } else {
        __half2 h01 = __floats2half2_rn(acc.x, acc.y);
        __half2 h23 = __floats2half2_rn(acc.z, acc.w);
        uint2 st;
        st.x = *(unsigned*)&h01;
        st.y = *(unsigned*)&h23;
        ((uint2*)(hout16 + (size_t)i * DD))[lane] = st;
    }
}

// ---------------- launch ----------------
extern "C" void kernel_launch(void* const* d_in, const int* in_sizes, int n_in,
                              void* d_out, int out_size) {
    const float* x  = (const float*)d_in[0];
    const void*  ei = (const void*)d_in[1];
    const float* W  = (const float*)d_in[2];
    const float* b  = (const float*)d_in[3];
    for (int i = 0; i < n_in; i++) {
        switch (in_sizes[i]) {
            case NN * DD:   x  = (const float*)d_in[i]; break;
            case 2 * EE:    ei = (const void*)d_in[i];  break;
            case DD * DD:   W  = (const float*)d_in[i]; break;
            case DD:        b  = (const float*)d_in[i]; break;
            default: break;
        }
    }
    float* out = (float*)d_out;
    (void)out_size;

    void *p_counts, *p_rowptr, *p_cursor, *p_bsums, *p_dinv, *p_esrc, *p_ew,
         *p_ha, *p_hb, *p_is64, *p_wh;
    cudaGetSymbolAddress(&p_counts, g_counts);
    cudaGetSymbolAddress(&p_rowptr, g_rowptr);
    cudaGetSymbolAddress(&p_cursor, g_cursor);
    cudaGetSymbolAddress(&p_bsums,  g_bsums);
    cudaGetSymbolAddress(&p_dinv,   g_dinv);
    cudaGetSymbolAddress(&p_esrc,   g_esrc);
    cudaGetSymbolAddress(&p_ew,     g_ew);
    cudaGetSymbolAddress(&p_ha,     g_ha);
    cudaGetSymbolAddress(&p_hb,     g_hb);
    cudaGetSymbolAddress(&p_is64,   g_is64);
    cudaGetSymbolAddress(&p_wh,     g_Wh);
    int*    counts = (int*)p_counts;
    int*    rowptr = (int*)p_rowptr;
    int*    cursor = (int*)p_cursor;
    int*    bsums  = (int*)p_bsums;
    float*  dinv   = (float*)p_dinv;
    int*    esrc   = (int*)p_esrc;
    float*  ew     = (float*)p_ew;
    __half* ha     = (__half*)p_ha;
    __half* hb     = (__half*)p_hb;
    int*    is64   = (int*)p_is64;
    __half* wh     = (__half*)p_wh;

    static cudaStream_t s_side = nullptr;
    static cudaEvent_t  s_fork = nullptr, s_join = nullptr;
    if (s_side == nullptr) {
        cudaStreamCreateWithFlags(&s_side, cudaStreamNonBlocking);
        cudaEventCreateWithFlags(&s_fork, cudaEventDisableTiming);
        cudaEventCreateWithFlags(&s_join, cudaEventDisableTiming);
    }

    // Fork: dense chain (wh -> gemm) runs concurrently with CSR build.
    cudaEventRecord(s_fork, 0);
    cudaStreamWaitEvent(s_side, s_fork, 0);
    k_wh  <<<(DD * DD + 255) / 256, 256, 0, s_side>>>(W, wh);
    k_gemm<<<(NN + GEMM_M - 1) / GEMM_M, 128, 0, s_side>>>(x, wh, ha);
    cudaEventRecord(s_join, s_side);

    // CSR build on the main (legacy) stream.
    k_detect_zero<<<(NN + 255) / 256, 256>>>((const unsigned*)ei, is64, counts);
    k_count<<<(EE + 255) / 256, 256>>>(ei, is64, counts);
    k_scan1<<<NB_SCAN, 256>>>(counts, rowptr, bsums);
    k_scan2<<<1, 32>>>(bsums, rowptr);
    k_scan3<<<(NN + 255) / 256, 256>>>(counts, rowptr, bsums, cursor, dinv);
    k_fill <<<(EE + 255) / 256, 256>>>(ei, is64, cursor, dinv, esrc, ew);

    cudaStreamWaitEvent(0, s_join, 0);

    const int hop_blocks = (NN * 32 + 255) / 256;
    k_hop<false><<<hop_blocks, 256>>>(ha, hb, nullptr, rowptr, dinv, esrc, ew, nullptr);
    k_hop<false><<<hop_blocks, 256>>>(hb, ha, nullptr, rowptr, dinv, esrc, ew, nullptr);
    k_hop<true> <<<hop_blocks, 256>>>(ha, nullptr, out, rowptr, dinv, esrc, ew, b);
}

// round 16
// speedup vs baseline: 1.9072x; 1.0038x over previous
#include <cuda_runtime.h>
#include <cuda_fp16.h>

#define NN 100000
#define EE 800000
#define DD 128
#define NB_SCAN ((NN + 1023) / 1024)
#define GEMM_M 64

typedef long long ll;
typedef unsigned long long ull;

// ---------------- scratch (device globals; no runtime allocation) ----------------
__device__ int    g_counts[NN];
__device__ int    g_rowptr[NN + 1];
__device__ int    g_cursor[NN];
__device__ int    g_bsums[NB_SCAN];
__device__ float  g_dinv[NN];
__device__ int    g_esrc[EE];
__device__ float  g_ew[EE];
__device__ int    g_is64;
__device__ __align__(16) __half g_Wh[DD * DD];
__device__ __align__(16) __half g_ha[(size_t)NN * DD];
__device__ __align__(16) __half g_hb[(size_t)NN * DD];

// ---------------- dtype detect + zero counts (fused) ----------------
__global__ void k_detect_zero(const unsigned* __restrict__ ei_words,
                              int* __restrict__ flag,
                              int* __restrict__ counts) {
    int i = blockIdx.x * blockDim.x + threadIdx.x;
    if (i < NN) counts[i] = 0;
    if (blockIdx.x == 0) {
        __shared__ int zc;
        if (threadIdx.x == 0) zc = 0;
        __syncthreads();
        int z = 0;
        for (int j = threadIdx.x; j < 1024; j += blockDim.x)
            if (ei_words[2 * j + 1] == 0u) z++;
        atomicAdd(&zc, z);
        __syncthreads();
        if (threadIdx.x == 0) *flag = (zc >= 1000) ? 1 : 0;
    }
}

// ---------------- degree count: 2 edges per thread ----------------
__global__ void k_count(const void* __restrict__ ei, const int* __restrict__ flag,
                        int* __restrict__ counts) {
    int p = blockIdx.x * blockDim.x + threadIdx.x;      // pair index
    if (2 * p < EE) {
        int is64 = *flag;
        int d0, d1;
        if (is64) {
            longlong2 v = ((const longlong2*)ei)[EE / 2 + p];
            d0 = (int)v.x; d1 = (int)v.y;
        } else {
            int2 v = ((const int2*)((const int*)ei + EE))[p];
            d0 = v.x; d1 = v.y;
        }
        if ((unsigned)d0 < (unsigned)NN) atomicAdd(&counts[d0], 1);
        if ((unsigned)d1 < (unsigned)NN) atomicAdd(&counts[d1], 1);
    }
}

__global__ void k_scan1(const int* __restrict__ counts,
                        int* __restrict__ rowptr,
                        int* __restrict__ bsums) {
    __shared__ int wsums[9];
    int t = threadIdx.x;
    int base = blockIdx.x * 1024 + t * 4;
    int v0 = 0, v1 = 0, v2 = 0, v3 = 0;
    if (base + 0 < NN) v0 = counts[base + 0];
    if (base + 1 < NN) v1 = counts[base + 1];
    if (base + 2 < NN) v2 = counts[base + 2];
    if (base + 3 < NN) v3 = counts[base + 3];
    int loc = v0 + v1 + v2 + v3;

    int lane = t & 31, w = t >> 5;
    int s = loc;
    #pragma unroll
    for (int d = 1; d < 32; d <<= 1) {
        int n = __shfl_up_sync(0xffffffffu, s, d);
        if (lane >= d) s += n;
    }
    if (lane == 31) wsums[w] = s;
    __syncthreads();
    if (t == 0) {
        int acc = 0;
        #pragma unroll
        for (int j = 0; j < 8; j++) { int x = wsums[j]; wsums[j] = acc; acc += x; }
        wsums[8] = acc;
    }
    __syncthreads();
    int excl = s - loc + wsums[w];
    if (base + 0 < NN) { rowptr[base + 0] = excl; excl += v0; }
    if (base + 1 < NN) { rowptr[base + 1] = excl; excl += v1; }
    if (base + 2 < NN) { rowptr[base + 2] = excl; excl += v2; }
    if (base + 3 < NN) { rowptr[base + 3] = excl; excl += v3; }
    if (t == 0) bsums[blockIdx.x] = wsums[8];
}

// scan3 with scan2 fused: each block covers 256 nodes = one 1024-segment slice,
// so it reduces bsums[0..seg-1] cooperatively (<=97 loads).
__global__ void k_scan3(const int* __restrict__ counts,
                        int* __restrict__ rowptr,
                        const int* __restrict__ bsums,
                        int* __restrict__ cursor,
                        float* __restrict__ dinv) {
    __shared__ int wsum[8];
    __shared__ int s_prefix;
    int t   = threadIdx.x;
    int blk = blockIdx.x;
    int seg = blk >> 2;                 // (blk*256)>>10

    int part = 0;
    for (int j = t; j < seg; j += 256) part += bsums[j];
    #pragma unroll
    for (int d = 16; d; d >>= 1) part += __shfl_down_sync(0xffffffffu, part, d);
    if ((t & 31) == 0) wsum[t >> 5] = part;
    __syncthreads();
    if (t == 0) {
        int a = 0;
        #pragma unroll
        for (int j = 0; j < 8; j++) a += wsum[j];
        s_prefix = a;
    }
    __syncthreads();
    int prefix = s_prefix;

    int i = blk * 256 + t;
    if (i < NN) {
        int r = rowptr[i] + prefix;
        rowptr[i] = r;
        cursor[i] = r;
        dinv[i]   = rsqrtf((float)(counts[i] + 1));   // +1 self-loop
    }
    if (blk == gridDim.x - 1 && t == 0)
        rowptr[NN] = prefix + bsums[seg];             // seg == NB_SCAN-1 here
}

// ---------------- fill: 2 edges per thread ----------------
__global__ void k_fill(const void* __restrict__ ei, const int* __restrict__ flag,
                       int* __restrict__ cursor,
                       const float* __restrict__ dinv,
                       int* __restrict__ esrc,
                       float* __restrict__ ew) {
    int p = blockIdx.x * blockDim.x + threadIdx.x;
    if (2 * p < EE) {
        int is64 = *flag;
        int s0, s1, d0, d1;
        if (is64) {
            longlong2 sv = ((const longlong2*)ei)[p];
            longlong2 dv = ((const longlong2*)ei)[EE / 2 + p];
            s0 = (int)sv.x; s1 = (int)sv.y;
            d0 = (int)dv.x; d1 = (int)dv.y;
        } else {
            int2 sv = ((const int2*)ei)[p];
            int2 dv = ((const int2*)((const int*)ei + EE))[p];
            s0 = sv.x; s1 = sv.y;
            d0 = dv.x; d1 = dv.y;
        }
        if ((unsigned)s0 < (unsigned)NN && (unsigned)d0 < (unsigned)NN) {
            int pos = atomicAdd(&cursor[d0], 1);
            if ((unsigned)pos < (unsigned)EE) {
                esrc[pos] = s0;
                ew[pos]   = dinv[s0] * dinv[d0];
            }
        }
        if ((unsigned)s1 < (unsigned)NN && (unsigned)d1 < (unsigned)NN) {
            int pos = atomicAdd(&cursor[d1], 1);
            if ((unsigned)pos < (unsigned)EE) {
                esrc[pos] = s1;
                ew[pos]   = dinv[s1] * dinv[d1];
            }
        }
    }
}

// ---------------- W -> fp16 ----------------
__global__ void k_wh(const float* __restrict__ W, __half* __restrict__ Wh) {
    int i = blockIdx.x * blockDim.x + threadIdx.x;
    if (i < DD * DD) Wh[i] = __float2half(W[i]);
}

// ---------------- tensor-core helpers ----------------
__device__ __forceinline__ void ldsm_x4(unsigned& r0, unsigned& r1, unsigned& r2, unsigned& r3,
                                        unsigned addr) {
    asm volatile("ldmatrix.sync.aligned.m8n8.x4.shared.b16 {%0,%1,%2,%3}, [%4];"
                 : "=r"(r0), "=r"(r1), "=r"(r2), "=r"(r3) : "r"(addr));
}
__device__ __forceinline__ void mma16816(float* d,
                                         unsigned a0, unsigned a1, unsigned a2, unsigned a3,
                                         unsigned b0, unsigned b1) {
    asm volatile("mma.sync.aligned.m16n8k16.row.col.f32.f16.f16.f32 "
                 "{%0,%1,%2,%3}, {%4,%5,%6,%7}, {%8,%9}, {%0,%1,%2,%3};"
                 : "+f"(d[0]), "+f"(d[1]), "+f"(d[2]), "+f"(d[3])
                 : "r"(a0), "r"(a1), "r"(a2), "r"(a3), "r"(b0), "r"(b1));
}

// ---------------- dense: H0 = fp16( X @ W^T ), HMMA ----------------
__global__ __launch_bounds__(128) void k_gemm(const float* __restrict__ X,
                                              const __half* __restrict__ Wh,
                                              __half* __restrict__ H0) {
    __shared__ __align__(16) __half As[GEMM_M * DD];
    __shared__ __align__(16) __half Bs[DD * DD];
    int t = threadIdx.x;
    int warp = t >> 5, lane = t & 31;
    int m0 = blockIdx.x * GEMM_M;

    #pragma unroll
    for (int r = 0; r < 8; r++) {
        int idx = t + 128 * r;
        int row = idx >> 4, c = idx & 15;
        int gr = m0 + row; if (gr >= NN) gr = NN - 1;
        const float4* src = (const float4*)(X + (size_t)gr * DD + c * 8);
        float4 v0 = src[0], v1 = src[1];
        __half2 h0 = __floats2half2_rn(v0.x, v0.y);
        __half2 h1 = __floats2half2_rn(v0.z, v0.w);
        __half2 h2 = __floats2half2_rn(v1.x, v1.y);
        __half2 h3 = __floats2half2_rn(v1.z, v1.w);
        uint4 st;
        st.x = *(unsigned*)&h0; st.y = *(unsigned*)&h1;
        st.z = *(unsigned*)&h2; st.w = *(unsigned*)&h3;
        int sc = c ^ (row & 7);
        *(uint4*)((char*)As + row * 256 + sc * 16) = st;
    }
    #pragma unroll
    for (int r = 0; r < 16; r++) {
        int idx = t + 128 * r;
        int row = idx >> 4, c = idx & 15;
        uint4 v = *(const uint4*)(Wh + (size_t)row * DD + c * 8);
        int sc = c ^ (row & 7);
        *(uint4*)((char*)Bs + row * 256 + sc * 16) = v;
    }
    __syncthreads();

    unsigned As_base = (unsigned)__cvta_generic_to_shared(As);
    unsigned Bs_base = (unsigned)__cvta_generic_to_shared(Bs);
    int grp = lane >> 3, lr = lane & 7;
    int mrow = warp * 16;
    float d[16][4] = {};

    #pragma unroll
    for (int ks = 0; ks < 8; ks++) {
        int arow = mrow + lr + ((grp & 1) ? 8 : 0);
        int achk = 2 * ks + ((grp & 2) ? 1 : 0);
        unsigned aaddr = As_base + arow * 256 + ((achk ^ (arow & 7)) * 16);
        unsigned a0, a1, a2, a3;
        ldsm_x4(a0, a1, a2, a3, aaddr);
        #pragma unroll
        for (int jj = 0; jj < 8; jj++) {
            int nt = jj * 2;
            int brow = nt * 8 + lr + ((grp & 2) ? 8 : 0);
            int bchk = 2 * ks + (grp & 1);
            unsigned baddr = Bs_base + brow * 256 + ((bchk ^ (brow & 7)) * 16);
            unsigned b0, b1, b2, b3;
            ldsm_x4(b0, b1, b2, b3, baddr);
            mma16816(d[nt],     a0, a1, a2, a3, b0, b1);
            mma16816(d[nt + 1], a0, a1, a2, a3, b2, b3);
        }
    }

    int orow = m0 + mrow + (lane >> 2);
    int ocol = 2 * (lane & 3);
    #pragma unroll
    for (int j = 0; j < 16; j++) {
        __half2 lo = __floats2half2_rn(d[j][0], d[j][1]);
        __half2 hi = __floats2half2_rn(d[j][2], d[j][3]);
        if (orow < NN)     *(__half2*)(H0 + (size_t)orow * DD + j * 8 + ocol) = lo;
        if (orow + 8 < NN) *(__half2*)(H0 + (size_t)(orow + 8) * DD + j * 8 + ocol) = hi;
    }
}

// ---------------- sparse hop: one warp per node, fp16 gather, fp32 accumulate ----------------
template <bool FINAL>
__global__ void k_hop(const __half* __restrict__ hin,
                      __half* __restrict__ hout16,
                      float* __restrict__ outf,
                      const int* __restrict__ rowptr,
                      const float* __restrict__ dinv,
                      const int* __restrict__ esrc,
                      const float* __restrict__ ew,
                      const float* __restrict__ bias) {
    int warp = (blockIdx.x * blockDim.x + threadIdx.x) >> 5;
    int lane = threadIdx.x & 31;
    if (warp >= NN) return;
    int i = warp;

    int start = rowptr[i];
    int end   = rowptr[i + 1];
    float di  = dinv[i];
    float sw  = di * di;

    uint2 su = ((const uint2*)(hin + (size_t)i * DD))[lane];
    float2 f01 = __half22float2(*(__half2*)&su.x);
    float2 f23 = __half22float2(*(__half2*)&su.y);
    float4 acc;
    acc.x = sw * f01.x; acc.y = sw * f01.y; acc.z = sw * f23.x; acc.w = sw * f23.y;

    for (int eb = start; eb < end; eb += 32) {
        int e = eb + lane;
        int s = 0; float w = 0.f;
        if (e < end) { s = esrc[e]; w = ew[e]; }
        int cnt = min(32, end - eb);
        int j = 0;
        for (; j + 2 <= cnt; j += 2) {
            int   s0 = __shfl_sync(0xffffffffu, s, j);
            int   s1 = __shfl_sync(0xffffffffu, s, j + 1);
            float w0 = __shfl_sync(0xffffffffu, w, j);
            float w1 = __shfl_sync(0xffffffffu, w, j + 1);
            uint2 u0 = ((const uint2*)(hin + (size_t)s0 * DD))[lane];
            uint2 u1 = ((const uint2*)(hin + (size_t)s1 * DD))[lane];
            float2 a01 = __half22float2(*(__half2*)&u0.x);
            float2 a23 = __half22float2(*(__half2*)&u0.y);
            float2 b01 = __half22float2(*(__half2*)&u1.x);
            float2 b23 = __half22float2(*(__half2*)&u1.y);
            acc.x += w0 * a01.x + w1 * b01.x;
            acc.y += w0 * a01.y + w1 * b01.y;
            acc.z += w0 * a23.x + w1 * b23.x;
            acc.w += w0 * a23.y + w1 * b23.y;
        }
        if (j < cnt) {
            int   sj = __shfl_sync(0xffffffffu, s, j);
            float wj = __shfl_sync(0xffffffffu, w, j);
            uint2 u0 = ((const uint2*)(hin + (size_t)sj * DD))[lane];
            float2 a01 = __half22float2(*(__half2*)&u0.x);
            float2 a23 = __half22float2(*(__half2*)&u0.y);
            acc.x += wj * a01.x; acc.y += wj * a01.y;
            acc.z += wj * a23.x; acc.w += wj * a23.y;
        }
    }

    if (FINAL) {
        float4 b4 = *(const float4*)(bias + lane * 4);
        acc.x += b4.x; acc.y += b4.y; acc.z += b4.z; acc.w += b4.w;
        *(float4*)(outf + (size_t)i * DD + lane * 4) = acc;
    } else {
        __half2 h01 = __floats2half2_rn(acc.x, acc.y);
        __half2 h23 = __floats2half2_rn(acc.z, acc.w);
        uint2 st;
        st.x = *(unsigned*)&h01;
        st.y = *(unsigned*)&h23;
        ((uint2*)(hout16 + (size_t)i * DD))[lane] = st;
    }
}

// ---------------- launch ----------------
extern "C" void kernel_launch(void* const* d_in, const int* in_sizes, int n_in,
                              void* d_out, int out_size) {
    const float* x  = (const float*)d_in[0];
    const void*  ei = (const void*)d_in[1];
    const float* W  = (const float*)d_in[2];
    const float* b  = (const float*)d_in[3];
    for (int i = 0; i < n_in; i++) {
        switch (in_sizes[i]) {
            case NN * DD:   x  = (const float*)d_in[i]; break;
            case 2 * EE:    ei = (const void*)d_in[i];  break;
            case DD * DD:   W  = (const float*)d_in[i]; break;
            case DD:        b  = (const float*)d_in[i]; break;
            default: break;
        }
    }
    float* out = (float*)d_out;
    (void)out_size;

    void *p_counts, *p_rowptr, *p_cursor, *p_bsums, *p_dinv, *p_esrc, *p_ew,
         *p_ha, *p_hb, *p_is64, *p_wh;
    cudaGetSymbolAddress(&p_counts, g_counts);
    cudaGetSymbolAddress(&p_rowptr, g_rowptr);
    cudaGetSymbolAddress(&p_cursor, g_cursor);
    cudaGetSymbolAddress(&p_bsums,  g_bsums);
    cudaGetSymbolAddress(&p_dinv,   g_dinv);
    cudaGetSymbolAddress(&p_esrc,   g_esrc);
    cudaGetSymbolAddress(&p_ew,     g_ew);
    cudaGetSymbolAddress(&p_ha,     g_ha);
    cudaGetSymbolAddress(&p_hb,     g_hb);
    cudaGetSymbolAddress(&p_is64,   g_is64);
    cudaGetSymbolAddress(&p_wh,     g_Wh);
    int*    counts = (int*)p_counts;
    int*    rowptr = (int*)p_rowptr;
    int*    cursor = (int*)p_cursor;
    int*    bsums  = (int*)p_bsums;
    float*  dinv   = (float*)p_dinv;
    int*    esrc   = (int*)p_esrc;
    float*  ew     = (float*)p_ew;
    __half* ha     = (__half*)p_ha;
    __half* hb     = (__half*)p_hb;
    int*    is64   = (int*)p_is64;
    __half* wh     = (__half*)p_wh;

    static cudaStream_t s_side = nullptr;
    static cudaEvent_t  s_fork = nullptr, s_join = nullptr;
    if (s_side == nullptr) {
        cudaStreamCreateWithFlags(&s_side, cudaStreamNonBlocking);
        cudaEventCreateWithFlags(&s_fork, cudaEventDisableTiming);
        cudaEventCreateWithFlags(&s_join, cudaEventDisableTiming);
    }

    // Fork: dense chain (wh -> gemm) runs concurrently with CSR build.
    cudaEventRecord(s_fork, 0);
    cudaStreamWaitEvent(s_side, s_fork, 0);
    k_wh  <<<(DD * DD + 255) / 256, 256, 0, s_side>>>(W, wh);
    k_gemm<<<(NN + GEMM_M - 1) / GEMM_M, 128, 0, s_side>>>(x, wh, ha);
    cudaEventRecord(s_join, s_side);

    // CSR build on the main (legacy) stream.
    k_detect_zero<<<(NN + 255) / 256, 256>>>((const unsigned*)ei, is64, counts);
    k_count<<<(EE / 2 + 255) / 256, 256>>>(ei, is64, counts);
    k_scan1<<<NB_SCAN, 256>>>(counts, rowptr, bsums);
    k_scan3<<<(NN + 255) / 256, 256>>>(counts, rowptr, bsums, cursor, dinv);
    k_fill <<<(EE / 2 + 255) / 256, 256>>>(ei, is64, cursor, dinv, esrc, ew);

    cudaStreamWaitEvent(0, s_join, 0);

    const int hop_blocks = (NN * 32 + 255) / 256;
    k_hop<false><<<hop_blocks, 256>>>(ha, hb, nullptr, rowptr, dinv, esrc, ew, nullptr);
    k_hop<false><<<hop_blocks, 256>>>(hb, ha, nullptr, rowptr, dinv, esrc, ew, nullptr);
    k_hop<true> <<<hop_blocks, 256>>>(ha, nullptr, out, rowptr, dinv, esrc, ew, b);
}